// round 7
// baseline (speedup 1.0000x reference)
#include <cuda_runtime.h>
#include <cuda_bf16.h>
#include <cstdint>
#include <math.h>

// Problem constants
#define B_SZ   2
#define S_LEN  2048
#define E_DIM  1024
#define H_NUM  16
#define D_HEAD 64
#define ALPHA  0.5f
#define LOG2E  1.4426950408889634f

#define GM 4096
#define GN 1024
#define GK 1024

// Scratch (device globals — allocation-free)
__device__ float g_X [GM * GK];          // x, tf32
__device__ float g_Wq[GN * GK];          // Wq * 0.125*log2e, tf32
__device__ float g_Wk[GN * GK];
__device__ float g_Wv[GN * GK];
__device__ float g_Wo[GN * GK];
__device__ float g_Q [GM * GN];          // tf32, pre-scaled, [b*S+s][h*64+d]
__device__ float g_K [GM * GN];          // tf32, [b*S+s][h*64+d]
__device__ float g_V [GM * GN];          // tf32, TRANSPOSED: [(b*1024 + h*64+d)][s]
__device__ float g_A [GM * GN];          // attention out, tf32

// ---------------------------------------------------------------------------
// Helpers
// ---------------------------------------------------------------------------
static __device__ __forceinline__ uint32_t smem_u32(const void* p) {
    uint32_t a;
    asm("{ .reg .u64 t; cvta.to.shared.u64 t, %1; cvt.u32.u64 %0, t; }" : "=r"(a) : "l"(p));
    return a;
}
static __device__ __forceinline__ float to_tf32(float f) {
    uint32_t u;
    asm("cvt.rna.tf32.f32 %0, %1;" : "=r"(u) : "f"(f));
    return __uint_as_float(u);
}
static __device__ __forceinline__ float ex2(float x) {
    float y;
    asm("ex2.approx.f32 %0, %1;" : "=f"(y) : "f"(x));
    return y;
}
static __device__ __forceinline__ void cp16(uint32_t dst, const void* src) {
    asm volatile("cp.async.cg.shared.global [%0], [%1], 16;" :: "r"(dst), "l"(src));
}
static __device__ __forceinline__ void cp_commit() {
    asm volatile("cp.async.commit_group;" ::: "memory");
}
static __device__ __forceinline__ void cp_wait0() {
    asm volatile("cp.async.wait_group 0;" ::: "memory");
}
static __device__ __forceinline__ void cp_wait1() {
    asm volatile("cp.async.wait_group 1;" ::: "memory");
}
#define LDSM4(R, ADDR)                                                        \
    asm volatile("ldmatrix.sync.aligned.m8n8.x4.shared.b16 {%0,%1,%2,%3}, [%4];" \
        : "=r"((R)[0]), "=r"((R)[1]), "=r"((R)[2]), "=r"((R)[3]) : "r"(ADDR))

static __device__ __forceinline__ void mma4(float* d, const uint32_t* a,
                                            uint32_t b0, uint32_t b1) {
    asm volatile(
        "mma.sync.aligned.m16n8k8.row.col.f32.tf32.tf32.f32 "
        "{%0,%1,%2,%3}, {%4,%5,%6,%7}, {%8,%9}, {%0,%1,%2,%3};"
        : "+f"(d[0]), "+f"(d[1]), "+f"(d[2]), "+f"(d[3])
        : "r"(a[0]), "r"(a[1]), "r"(a[2]), "r"(a[3]), "r"(b0), "r"(b1));
}

// ---------------------------------------------------------------------------
// Pre-convert inputs to TF32 (scale folded for Wq)
// ---------------------------------------------------------------------------
__global__ __launch_bounds__(256)
void cvt_kernel(const float4* __restrict__ x,  const float4* __restrict__ wq,
                const float4* __restrict__ wk, const float4* __restrict__ wv,
                const float4* __restrict__ wo)
{
    const int z = blockIdx.z;
    const float4* src;
    float4* dst;
    int n4;
    float s = 1.0f;
    switch (z) {
        case 0: src = x;  dst = (float4*)g_X;  n4 = GM * GK / 4; break;
        case 1: src = wq; dst = (float4*)g_Wq; n4 = GN * GK / 4; s = 0.125f * LOG2E; break;
        case 2: src = wk; dst = (float4*)g_Wk; n4 = GN * GK / 4; break;
        case 3: src = wv; dst = (float4*)g_Wv; n4 = GN * GK / 4; break;
        default: src = wo; dst = (float4*)g_Wo; n4 = GN * GK / 4; break;
    }
    for (int i = blockIdx.x * 256 + threadIdx.x; i < n4; i += gridDim.x * 256) {
        float4 v = src[i];
        v.x = to_tf32(v.x * s); v.y = to_tf32(v.y * s);
        v.z = to_tf32(v.z * s); v.w = to_tf32(v.w * s);
        dst[i] = v;
    }
}

// ---------------------------------------------------------------------------
// TF32 GEMM: C = A[M,K] @ W[N,K]^T (tf32-formatted inputs).
// CTA 128x128, 128 threads (4 warps, 2x2), warp tile 64x64, K-chunk 32,
// 3-stage cp.async pipeline, ldmatrix fragment loads, XOR-swizzled smem.
// z==2 with cvt_out: V output stored TRANSPOSED ([b*1024+n][s]).
// ---------------------------------------------------------------------------
#define GEMM_SMEM (3 * 8192 * 4)

__global__ __launch_bounds__(128, 2)
void gemm_tc(const float* __restrict__ A,
             const float* __restrict__ W0, const float* __restrict__ W1,
             const float* __restrict__ W2,
             float* __restrict__ C0, float* __restrict__ C1, float* __restrict__ C2,
             int cvt_out)
{
    extern __shared__ float smf[];
    const uint32_t sb = smem_u32(smf);

    const float* W = (blockIdx.z == 0) ? W0 : (blockIdx.z == 1) ? W1 : W2;
    float*       C = (blockIdx.z == 0) ? C0 : (blockIdx.z == 1) ? C1 : C2;

    const int t    = threadIdx.x;
    const int w    = t >> 5;
    const int lane = t & 31;
    const int g    = lane >> 2;
    const int t4   = lane & 3;
    const int i7   = lane & 7;
    const int tq   = lane >> 3;
    const int m0   = (w >> 1) * 64;
    const int n0   = (w & 1) * 64;
    const int bm   = blockIdx.y * 128;
    const int bn   = blockIdx.x * 128;

    const uint32_t laneA = (uint32_t)(m0 + ((tq & 1) << 3) + i7) * 128;
    const uint32_t laneB = (uint32_t)(n0 + ((tq & 2) << 2) + i7) * 128;

    float acc[4][8][4];
#pragma unroll
    for (int mf = 0; mf < 4; mf++)
#pragma unroll
        for (int nf = 0; nf < 8; nf++)
#pragma unroll
            for (int r = 0; r < 4; r++) acc[mf][nf][r] = 0.0f;

#define GEMM_ISSUE(CH) do {                                                    \
        const int _k0 = (CH) * 32;                                             \
        const uint32_t _sa = sb + ((CH) % 3) * 32768;                          \
        _Pragma("unroll")                                                      \
        for (int _i = 0; _i < 8; _i++) {                                       \
            int _idx = _i * 128 + t;                                           \
            int _row = _idx >> 3;                                              \
            int _wd  = _idx & 7;                                               \
            uint32_t _o = (uint32_t)(_row * 128 + (((_wd) ^ (_row & 7)) << 4));\
            cp16(_sa + _o,         &A[(size_t)(bm + _row) * GK + _k0 + _wd * 4]); \
            cp16(_sa + 16384 + _o, &W[(size_t)(bn + _row) * GK + _k0 + _wd * 4]); \
        }                                                                      \
        cp_commit();                                                           \
    } while (0)

    GEMM_ISSUE(0);
    GEMM_ISSUE(1);

    for (int ch = 0; ch < 32; ch++) {
        if (ch < 31) cp_wait1(); else cp_wait0();
        __syncthreads();
        if (ch + 2 < 32) GEMM_ISSUE(ch + 2);

        const uint32_t stage = sb + (ch % 3) * 32768;
#pragma unroll
        for (int ks = 0; ks < 4; ks++) {
            const uint32_t cwA = (uint32_t)(((2 * ks + (tq >> 1)) ^ i7) << 4);
            const uint32_t cwB = (uint32_t)(((2 * ks + (tq & 1)) ^ i7) << 4);
            uint32_t av[4][4];
#pragma unroll
            for (int mf = 0; mf < 4; mf++)
                LDSM4(av[mf], stage + laneA + mf * 2048 + cwA);
            uint32_t bv[16];
#pragma unroll
            for (int np = 0; np < 4; np++)
                LDSM4(&bv[np * 4], stage + 16384 + laneB + np * 2048 + cwB);
#pragma unroll
            for (int nf = 0; nf < 8; nf++) {
                uint32_t b0 = bv[(nf >> 1) * 4 + (nf & 1) * 2];
                uint32_t b1 = bv[(nf >> 1) * 4 + (nf & 1) * 2 + 1];
#pragma unroll
                for (int mf = 0; mf < 4; mf++)
                    mma4(acc[mf][nf], av[mf], b0, b1);
            }
        }
    }

    // epilogue
    if (cvt_out && blockIdx.z == 2) {
        // V: transposed tf32 store -> C[(b*1024 + n)][s], s = row % 2048
        const int bb = bm >> 11;                 // batch (constant per CTA)
#pragma unroll
        for (int mf = 0; mf < 4; mf++) {
            int row = bm + m0 + mf * 16 + g;
            int s   = row & (S_LEN - 1);
#pragma unroll
            for (int nf = 0; nf < 8; nf++) {
                int col = bn + n0 + nf * 8 + 2 * t4;
                size_t base = ((size_t)(bb * 1024 + col)) * S_LEN + s;
                C[base]               = to_tf32(acc[mf][nf][0]);
                C[base + S_LEN]       = to_tf32(acc[mf][nf][1]);
                C[base + 8]           = to_tf32(acc[mf][nf][2]);
                C[base + S_LEN + 8]   = to_tf32(acc[mf][nf][3]);
            }
        }
    } else {
#pragma unroll
        for (int mf = 0; mf < 4; mf++) {
            int row = bm + m0 + mf * 16 + g;
#pragma unroll
            for (int nf = 0; nf < 8; nf++) {
                int col = bn + n0 + nf * 8 + 2 * t4;
                float v0 = acc[mf][nf][0], v1 = acc[mf][nf][1];
                float v2 = acc[mf][nf][2], v3 = acc[mf][nf][3];
                if (cvt_out) {
                    v0 = to_tf32(v0); v1 = to_tf32(v1);
                    v2 = to_tf32(v2); v3 = to_tf32(v3);
                }
                *(float2*)&C[(size_t)row * GN + col]       = make_float2(v0, v1);
                *(float2*)&C[(size_t)(row + 8) * GN + col] = make_float2(v2, v3);
            }
        }
    }
#undef GEMM_ISSUE
}

// ---------------------------------------------------------------------------
// TF32 flash attention, exp2-domain online softmax, pipelined cp.async KV,
// ldmatrix fragments for Q, K, P AND V (V is pre-transposed in gmem).
// 256 threads (8 warps); CTA = 128 queries of one (b,h); warp = 16 q-rows.
// SMEM bytes: Q @0 (32K), K0 @32768, K1 @49152, V @65536 (16K each),
//             P @81920 (32K), madd @114688 (512).  Total 115,200 B.
// ---------------------------------------------------------------------------
#define ATT_SMEM 115200

__global__ __launch_bounds__(256, 2)
void attn_tc(const unsigned int* __restrict__ mask, float* __restrict__ out)
{
    extern __shared__ float smf[];
    const uint32_t sb  = smem_u32(smf);
    const uint32_t QB  = sb;
    const uint32_t KB0 = sb + 32768;
    const uint32_t KB1 = sb + 49152;
    const uint32_t VB  = sb + 65536;
    const uint32_t PB  = sb + 81920;
    float* maddf = smf + 28672;

    const int t    = threadIdx.x;
    const int w    = t >> 5;
    const int lane = t & 31;
    const int g    = lane >> 2;
    const int t4   = lane & 3;
    const int i7   = lane & 7;
    const int tq   = lane >> 3;
    const int g4   = g << 2;
    const int q0   = blockIdx.x * 128;
    const int h    = blockIdx.y;
    const int b    = blockIdx.z;
    const int m0   = w * 16;               // 16 query rows per warp

    const float BSC = ALPHA * LOG2E / (float)S_LEN;

    // ldmatrix per-lane row bases (bytes; 256B rows)
    const uint32_t laneA = (uint32_t)(m0 + ((tq & 1) << 3) + i7) * 256;   // Q, P (16-row A frag)
    const uint32_t laneB = (uint32_t)(((tq & 2) << 2) + i7) * 256;        // K, V^T (B frags)

    // prologue: Q (8 cp16/thr) + K tile 0 (4 cp16/thr), one group
#pragma unroll
    for (int i = 0; i < 8; i++) {
        int idx = i * 256 + t;
        int row = idx >> 4;
        int wd  = idx & 15;
        cp16(QB + (uint32_t)(row * 256 + ((wd ^ (row & 7)) << 4)),
             &g_Q[((size_t)(b * S_LEN + q0 + row)) * E_DIM + h * D_HEAD + wd * 4]);
    }
#pragma unroll
    for (int i = 0; i < 4; i++) {
        int idx = i * 256 + t;
        int row = idx >> 4;
        int wd  = idx & 15;
        cp16(KB0 + (uint32_t)(row * 256 + ((wd ^ (row & 7)) << 4)),
             &g_K[((size_t)(b * S_LEN + row)) * E_DIM + h * D_HEAD + wd * 4]);
    }
    cp_commit();

    float o[8][4];
#pragma unroll
    for (int nf = 0; nf < 8; nf++)
#pragma unroll
        for (int r = 0; r < 4; r++) o[nf][r] = 0.0f;

    float mrow0 = -1e30f, mrow1 = -1e30f;
    float lrow0 = 0.0f,   lrow1 = 0.0f;
    const float tgt0 = (float)(S_LEN - 1 - (q0 + m0 + g));
    const float tgt1 = (float)(S_LEN - 1 - (q0 + m0 + 8 + g));

    for (int kt = 0; kt < 32; kt++) {
        const int k0g = kt * 64;
        const uint32_t KB = (kt & 1) ? KB1 : KB0;

        // 1. wait K(kt) (and Q on kt=0)
        cp_wait0();
        // 2. mask additive, double-buffered
        if (t < 64)
            maddf[(kt & 1) * 64 + t] = (mask[b * S_LEN + k0g + t] != 0u) ? -1e30f : 0.0f;
        // 3. all warps finished previous tile; K(kt) visible
        __syncthreads();
        // 4. issue V(kt): V^T rows = d (64), cols = s (64 keys)
#pragma unroll
        for (int i = 0; i < 4; i++) {
            int idx = i * 256 + t;
            int row = idx >> 4;     // d within head
            int wd  = idx & 15;     // s word
            cp16(VB + (uint32_t)(row * 256 + ((wd ^ (row & 7)) << 4)),
                 &g_V[((size_t)(b * 1024 + h * D_HEAD + row)) * S_LEN + k0g + wd * 4]);
        }
        cp_commit();

        // 5. S = Q @ K^T (exp2 domain; scale folded into Q)
        float sc[8][4];
#pragma unroll
        for (int nf = 0; nf < 8; nf++)
#pragma unroll
            for (int r = 0; r < 4; r++) sc[nf][r] = 0.0f;

#pragma unroll
        for (int ks = 0; ks < 8; ks++) {
            const uint32_t cwA = (uint32_t)(((2 * ks + (tq >> 1)) ^ i7) << 4);
            const uint32_t cwB = (uint32_t)(((2 * ks + (tq & 1)) ^ i7) << 4);
            uint32_t av[4];
            LDSM4(av, QB + laneA + cwA);
            uint32_t bv[16];
#pragma unroll
            for (int np = 0; np < 4; np++)
                LDSM4(&bv[np * 4], KB + laneB + np * 4096 + cwB);
#pragma unroll
            for (int nf = 0; nf < 8; nf++) {
                uint32_t b0 = bv[(nf >> 1) * 4 + (nf & 1) * 2];
                uint32_t b1 = bv[(nf >> 1) * 4 + (nf & 1) * 2 + 1];
                mma4(sc[nf], av, b0, b1);
            }
        }

        // 6. prefetch K(kt+1) into the other buffer
        if (kt < 31) {
            const uint32_t KBn = (kt & 1) ? KB0 : KB1;
#pragma unroll
            for (int i = 0; i < 4; i++) {
                int idx = i * 256 + t;
                int row = idx >> 4;
                int wd  = idx & 15;
                cp16(KBn + (uint32_t)(row * 256 + ((wd ^ (row & 7)) << 4)),
                     &g_K[((size_t)(b * S_LEN + k0g + 64 + row)) * E_DIM + h * D_HEAD + wd * 4]);
            }
            cp_commit();
        }

        // 7. bias + mask + online softmax + P store
        {
            const float* md = maddf + (kt & 1) * 64;
#pragma unroll
            for (int nf = 0; nf < 8; nf++) {
                int jc = nf * 8 + 2 * t4;
                float jk0 = (float)(k0g + jc);
                float ma0 = md[jc], ma1 = md[jc + 1];
                sc[nf][0] += -BSC * fabsf(jk0 - tgt0) + ma0;
                sc[nf][1] += -BSC * fabsf(jk0 + 1.0f - tgt0) + ma1;
                sc[nf][2] += -BSC * fabsf(jk0 - tgt1) + ma0;
                sc[nf][3] += -BSC * fabsf(jk0 + 1.0f - tgt1) + ma1;
            }
            float mx0 = -1e30f, mx1 = -1e30f;
#pragma unroll
            for (int nf = 0; nf < 8; nf++) {
                mx0 = fmaxf(mx0, fmaxf(sc[nf][0], sc[nf][1]));
                mx1 = fmaxf(mx1, fmaxf(sc[nf][2], sc[nf][3]));
            }
            mx0 = fmaxf(mx0, __shfl_xor_sync(0xffffffffu, mx0, 1));
            mx0 = fmaxf(mx0, __shfl_xor_sync(0xffffffffu, mx0, 2));
            mx1 = fmaxf(mx1, __shfl_xor_sync(0xffffffffu, mx1, 1));
            mx1 = fmaxf(mx1, __shfl_xor_sync(0xffffffffu, mx1, 2));

            float mnew0 = fmaxf(mrow0, mx0);
            float mnew1 = fmaxf(mrow1, mx1);
            float c0 = ex2(mrow0 - mnew0);
            float c1 = ex2(mrow1 - mnew1);
            mrow0 = mnew0; mrow1 = mnew1;

            float s0 = 0.0f, s1 = 0.0f;
            int r = m0 + g;
#pragma unroll
            for (int nf = 0; nf < 8; nf++) {
                float p0 = ex2(sc[nf][0] - mnew0);
                float p1 = ex2(sc[nf][1] - mnew0);
                float p2 = ex2(sc[nf][2] - mnew1);
                float p3 = ex2(sc[nf][3] - mnew1);
                s0 += p0 + p1;
                s1 += p2 + p3;
                int colx = (nf * 8 + 2 * t4) ^ g4;
                *(float2*)&smf[20480 + r * 64 + colx]       = make_float2(to_tf32(p0), to_tf32(p1));
                *(float2*)&smf[20480 + (r + 8) * 64 + colx] = make_float2(to_tf32(p2), to_tf32(p3));
            }
            s0 += __shfl_xor_sync(0xffffffffu, s0, 1);
            s0 += __shfl_xor_sync(0xffffffffu, s0, 2);
            s1 += __shfl_xor_sync(0xffffffffu, s1, 1);
            s1 += __shfl_xor_sync(0xffffffffu, s1, 2);
            lrow0 = lrow0 * c0 + s0;
            lrow1 = lrow1 * c1 + s1;
#pragma unroll
            for (int nf = 0; nf < 8; nf++) {
                o[nf][0] *= c0; o[nf][1] *= c0;
                o[nf][2] *= c1; o[nf][3] *= c1;
            }
        }
        __syncwarp();   // P stores visible to ldmatrix cross-lane

        // 8. wait V(kt) [K(kt+1) may stay pending], then make visible
        if (kt < 31) cp_wait1(); else cp_wait0();
        __syncthreads();

        // 9. O += P @ V  (V^T in smem: rows d, cols s -> same B frag as K)
#pragma unroll
        for (int ks = 0; ks < 8; ks++) {
            const uint32_t cwA = (uint32_t)(((2 * ks + (tq >> 1)) ^ i7) << 4);
            const uint32_t cwB = (uint32_t)(((2 * ks + (tq & 1)) ^ i7) << 4);
            uint32_t pv[4];
            LDSM4(pv, PB + laneA + cwA);
            uint32_t bv[16];
#pragma unroll
            for (int np = 0; np < 4; np++)
                LDSM4(&bv[np * 4], VB + laneB + np * 4096 + cwB);
#pragma unroll
            for (int nf = 0; nf < 8; nf++) {
                uint32_t b0 = bv[(nf >> 1) * 4 + (nf & 1) * 2];
                uint32_t b1 = bv[(nf >> 1) * 4 + (nf & 1) * 2 + 1];
                mma4(o[nf], pv, b0, b1);
            }
        }
        __syncwarp();
    }

    // ---- finalize (write tf32 so O-proj can cp.async raw) ----
    {
        float inv0 = 1.0f / lrow0;
        float inv1 = 1.0f / lrow1;
        size_t r0 = ((size_t)(b * S_LEN + q0 + m0 + g)) * E_DIM + h * D_HEAD;
        size_t r1 = r0 + 8 * E_DIM;
#pragma unroll
        for (int nf = 0; nf < 8; nf++) {
            int col = nf * 8 + 2 * t4;
            *(float2*)&out[r0 + col] =
                make_float2(to_tf32(o[nf][0] * inv0), to_tf32(o[nf][1] * inv0));
            *(float2*)&out[r1 + col] =
                make_float2(to_tf32(o[nf][2] * inv1), to_tf32(o[nf][3] * inv1));
        }
    }
}

// ---------------------------------------------------------------------------
extern "C" void kernel_launch(void* const* d_in, const int* in_sizes, int n_in,
                              void* d_out, int out_size)
{
    const float* x    = (const float*)d_in[0];
    const float* Wq   = (const float*)d_in[1];
    const float* Wk   = (const float*)d_in[2];
    const float* Wv   = (const float*)d_in[3];
    const float* Wo   = (const float*)d_in[4];
    const unsigned int* mask = (const unsigned int*)d_in[5];
    float* out = (float*)d_out;

    float *xp, *wqp, *wkp, *wvp, *wop, *qp, *kp, *vp, *ap;
    cudaGetSymbolAddress((void**)&xp,  g_X);
    cudaGetSymbolAddress((void**)&wqp, g_Wq);
    cudaGetSymbolAddress((void**)&wkp, g_Wk);
    cudaGetSymbolAddress((void**)&wvp, g_Wv);
    cudaGetSymbolAddress((void**)&wop, g_Wo);
    cudaGetSymbolAddress((void**)&qp,  g_Q);
    cudaGetSymbolAddress((void**)&kp,  g_K);
    cudaGetSymbolAddress((void**)&vp,  g_V);
    cudaGetSymbolAddress((void**)&ap,  g_A);

    cudaFuncSetAttribute(gemm_tc, cudaFuncAttributeMaxDynamicSharedMemorySize, GEMM_SMEM);
    cudaFuncSetAttribute(attn_tc, cudaFuncAttributeMaxDynamicSharedMemorySize, ATT_SMEM);

    // 1. pre-convert inputs to tf32 (Wq scaled by 0.125*log2e)
    cvt_kernel<<<dim3(512, 1, 5), 256>>>((const float4*)x, (const float4*)Wq,
                                         (const float4*)Wk, (const float4*)Wv,
                                         (const float4*)Wo);

    // 2. fused QKV projections (V written transposed)
    gemm_tc<<<dim3(GN / 128, GM / 128, 3), 128, GEMM_SMEM>>>(
        xp, wqp, wkp, wvp, qp, kp, vp, 1);

    // 3. attention (256 threads / 8 warps)
    attn_tc<<<dim3(S_LEN / 128, H_NUM, B_SZ), 256, ATT_SMEM>>>(mask, ap);

    // 4. output projection (fp32 out)
    gemm_tc<<<dim3(GN / 128, GM / 128, 1), 128, GEMM_SMEM>>>(
        ap, wop, wop, wop, out, out, out, 0);
}

// round 8
// speedup vs baseline: 1.1492x; 1.1492x over previous
#include <cuda_runtime.h>
#include <cuda_bf16.h>
#include <cstdint>
#include <math.h>

// Problem constants
#define B_SZ   2
#define S_LEN  2048
#define E_DIM  1024
#define H_NUM  16
#define D_HEAD 64
#define ALPHA  0.5f
#define LOG2E  1.4426950408889634f

#define GM 4096
#define GN 1024
#define GK 1024

// Scratch (device globals — allocation-free)
__device__ float g_X [GM * GK];          // x, tf32
__device__ float g_Wq[GN * GK];          // Wq * 0.125*log2e, tf32
__device__ float g_Wk[GN * GK];
__device__ float g_Wv[GN * GK];
__device__ float g_Wo[GN * GK];
__device__ float g_Q [GM * GN];          // tf32, pre-scaled, [b*S+s][h*64+d]
__device__ float g_K [GM * GN];          // tf32, [b*S+s][h*64+d]
__device__ float g_V [GM * GN];          // tf32, TRANSPOSED: [(b*1024 + h*64+d)][s]
__device__ float g_A [GM * GN];          // attention out, tf32

// ---------------------------------------------------------------------------
// Helpers
// ---------------------------------------------------------------------------
static __device__ __forceinline__ uint32_t smem_u32(const void* p) {
    uint32_t a;
    asm("{ .reg .u64 t; cvta.to.shared.u64 t, %1; cvt.u32.u64 %0, t; }" : "=r"(a) : "l"(p));
    return a;
}
static __device__ __forceinline__ float to_tf32(float f) {
    uint32_t u;
    asm("cvt.rna.tf32.f32 %0, %1;" : "=r"(u) : "f"(f));
    return __uint_as_float(u);
}
static __device__ __forceinline__ float ex2(float x) {
    float y;
    asm("ex2.approx.f32 %0, %1;" : "=f"(y) : "f"(x));
    return y;
}
static __device__ __forceinline__ void cp16(uint32_t dst, const void* src) {
    asm volatile("cp.async.cg.shared.global [%0], [%1], 16;" :: "r"(dst), "l"(src));
}
static __device__ __forceinline__ void cp_commit() {
    asm volatile("cp.async.commit_group;" ::: "memory");
}
static __device__ __forceinline__ void cp_wait0() {
    asm volatile("cp.async.wait_group 0;" ::: "memory");
}
static __device__ __forceinline__ void cp_wait1() {
    asm volatile("cp.async.wait_group 1;" ::: "memory");
}
#define LDSM4(R, ADDR)                                                        \
    asm volatile("ldmatrix.sync.aligned.m8n8.x4.shared.b16 {%0,%1,%2,%3}, [%4];" \
        : "=r"((R)[0]), "=r"((R)[1]), "=r"((R)[2]), "=r"((R)[3]) : "r"(ADDR))

static __device__ __forceinline__ void mma4(float* d, const uint32_t* a,
                                            uint32_t b0, uint32_t b1) {
    asm volatile(
        "mma.sync.aligned.m16n8k8.row.col.f32.tf32.tf32.f32 "
        "{%0,%1,%2,%3}, {%4,%5,%6,%7}, {%8,%9}, {%0,%1,%2,%3};"
        : "+f"(d[0]), "+f"(d[1]), "+f"(d[2]), "+f"(d[3])
        : "r"(a[0]), "r"(a[1]), "r"(a[2]), "r"(a[3]), "r"(b0), "r"(b1));
}

// ---------------------------------------------------------------------------
// Pre-convert inputs to TF32 (scale folded for Wq)
// ---------------------------------------------------------------------------
__global__ __launch_bounds__(256)
void cvt_kernel(const float4* __restrict__ x,  const float4* __restrict__ wq,
                const float4* __restrict__ wk, const float4* __restrict__ wv,
                const float4* __restrict__ wo)
{
    const int z = blockIdx.z;
    const float4* src;
    float4* dst;
    int n4;
    float s = 1.0f;
    switch (z) {
        case 0: src = x;  dst = (float4*)g_X;  n4 = GM * GK / 4; break;
        case 1: src = wq; dst = (float4*)g_Wq; n4 = GN * GK / 4; s = 0.125f * LOG2E; break;
        case 2: src = wk; dst = (float4*)g_Wk; n4 = GN * GK / 4; break;
        case 3: src = wv; dst = (float4*)g_Wv; n4 = GN * GK / 4; break;
        default: src = wo; dst = (float4*)g_Wo; n4 = GN * GK / 4; break;
    }
    for (int i = blockIdx.x * 256 + threadIdx.x; i < n4; i += gridDim.x * 256) {
        float4 v = src[i];
        v.x = to_tf32(v.x * s); v.y = to_tf32(v.y * s);
        v.z = to_tf32(v.z * s); v.w = to_tf32(v.w * s);
        dst[i] = v;
    }
}

// ---------------------------------------------------------------------------
// TF32 GEMM: C = A[M,K] @ W[N,K]^T (tf32-formatted inputs).
// CTA 128x128, 128 threads (4 warps, 2x2), warp tile 64x64, K-chunk 32,
// 3-stage cp.async pipeline, ldmatrix fragment loads, XOR-swizzled smem.
// z==2 with cvt_out: V output stored TRANSPOSED ([b*1024+n][s]).
// ---------------------------------------------------------------------------
#define GEMM_SMEM (3 * 8192 * 4)

__global__ __launch_bounds__(128, 2)
void gemm_tc(const float* __restrict__ A,
             const float* __restrict__ W0, const float* __restrict__ W1,
             const float* __restrict__ W2,
             float* __restrict__ C0, float* __restrict__ C1, float* __restrict__ C2,
             int cvt_out)
{
    extern __shared__ float smf[];
    const uint32_t sb = smem_u32(smf);

    const float* W = (blockIdx.z == 0) ? W0 : (blockIdx.z == 1) ? W1 : W2;
    float*       C = (blockIdx.z == 0) ? C0 : (blockIdx.z == 1) ? C1 : C2;

    const int t    = threadIdx.x;
    const int w    = t >> 5;
    const int lane = t & 31;
    const int g    = lane >> 2;
    const int t4   = lane & 3;
    const int i7   = lane & 7;
    const int tq   = lane >> 3;
    const int m0   = (w >> 1) * 64;
    const int n0   = (w & 1) * 64;
    const int bm   = blockIdx.y * 128;
    const int bn   = blockIdx.x * 128;

    const uint32_t laneA = (uint32_t)(m0 + ((tq & 1) << 3) + i7) * 128;
    const uint32_t laneB = (uint32_t)(n0 + ((tq & 2) << 2) + i7) * 128;

    float acc[4][8][4];
#pragma unroll
    for (int mf = 0; mf < 4; mf++)
#pragma unroll
        for (int nf = 0; nf < 8; nf++)
#pragma unroll
            for (int r = 0; r < 4; r++) acc[mf][nf][r] = 0.0f;

#define GEMM_ISSUE(CH) do {                                                    \
        const int _k0 = (CH) * 32;                                             \
        const uint32_t _sa = sb + ((CH) % 3) * 32768;                          \
        _Pragma("unroll")                                                      \
        for (int _i = 0; _i < 8; _i++) {                                       \
            int _idx = _i * 128 + t;                                           \
            int _row = _idx >> 3;                                              \
            int _wd  = _idx & 7;                                               \
            uint32_t _o = (uint32_t)(_row * 128 + (((_wd) ^ (_row & 7)) << 4));\
            cp16(_sa + _o,         &A[(size_t)(bm + _row) * GK + _k0 + _wd * 4]); \
            cp16(_sa + 16384 + _o, &W[(size_t)(bn + _row) * GK + _k0 + _wd * 4]); \
        }                                                                      \
        cp_commit();                                                           \
    } while (0)

    GEMM_ISSUE(0);
    GEMM_ISSUE(1);

    for (int ch = 0; ch < 32; ch++) {
        if (ch < 31) cp_wait1(); else cp_wait0();
        __syncthreads();
        if (ch + 2 < 32) GEMM_ISSUE(ch + 2);

        const uint32_t stage = sb + (ch % 3) * 32768;
#pragma unroll
        for (int ks = 0; ks < 4; ks++) {
            const uint32_t cwA = (uint32_t)(((2 * ks + (tq >> 1)) ^ i7) << 4);
            const uint32_t cwB = (uint32_t)(((2 * ks + (tq & 1)) ^ i7) << 4);
            uint32_t av[4][4];
#pragma unroll
            for (int mf = 0; mf < 4; mf++)
                LDSM4(av[mf], stage + laneA + mf * 2048 + cwA);
            uint32_t bv[16];
#pragma unroll
            for (int np = 0; np < 4; np++)
                LDSM4(&bv[np * 4], stage + 16384 + laneB + np * 2048 + cwB);
#pragma unroll
            for (int nf = 0; nf < 8; nf++) {
                uint32_t b0 = bv[(nf >> 1) * 4 + (nf & 1) * 2];
                uint32_t b1 = bv[(nf >> 1) * 4 + (nf & 1) * 2 + 1];
#pragma unroll
                for (int mf = 0; mf < 4; mf++)
                    mma4(acc[mf][nf], av[mf], b0, b1);
            }
        }
    }

    // epilogue
    if (cvt_out && blockIdx.z == 2) {
        // V: transposed tf32 store -> C[(b*1024 + n)][s], s = row % 2048
        const int bb = bm >> 11;
#pragma unroll
        for (int mf = 0; mf < 4; mf++) {
            int row = bm + m0 + mf * 16 + g;
            int s   = row & (S_LEN - 1);
#pragma unroll
            for (int nf = 0; nf < 8; nf++) {
                int col = bn + n0 + nf * 8 + 2 * t4;
                size_t base = ((size_t)(bb * 1024 + col)) * S_LEN + s;
                C[base]               = to_tf32(acc[mf][nf][0]);
                C[base + S_LEN]       = to_tf32(acc[mf][nf][1]);
                C[base + 8]           = to_tf32(acc[mf][nf][2]);
                C[base + S_LEN + 8]   = to_tf32(acc[mf][nf][3]);
            }
        }
    } else {
#pragma unroll
        for (int mf = 0; mf < 4; mf++) {
            int row = bm + m0 + mf * 16 + g;
#pragma unroll
            for (int nf = 0; nf < 8; nf++) {
                int col = bn + n0 + nf * 8 + 2 * t4;
                float v0 = acc[mf][nf][0], v1 = acc[mf][nf][1];
                float v2 = acc[mf][nf][2], v3 = acc[mf][nf][3];
                if (cvt_out) {
                    v0 = to_tf32(v0); v1 = to_tf32(v1);
                    v2 = to_tf32(v2); v3 = to_tf32(v3);
                }
                *(float2*)&C[(size_t)row * GN + col]       = make_float2(v0, v1);
                *(float2*)&C[(size_t)(row + 8) * GN + col] = make_float2(v2, v3);
            }
        }
    }
#undef GEMM_ISSUE
}

// ---------------------------------------------------------------------------
// TF32 flash attention, exp2-domain softmax WITHOUT running max (scores are
// bounded: |qk/8*log2e| < ~10, no overflow possible; masked -> ex2(-1e30)=0).
// 128 threads (4 warps); CTA = 128 queries of one (b,h); warp = 32 q-rows.
// K double-buffered + pipelined; V^T (pre-transposed) loaded via ldmatrix.
// SMEM bytes: Q @0 (32K), K0 @32768, K1 @49152, V @65536 (16K each),
//             P @81920 (32K), madd @114688 (512).  Total 115,200 B.
// ---------------------------------------------------------------------------
#define ATT_SMEM 115200

__global__ __launch_bounds__(128, 2)
void attn_tc(const unsigned int* __restrict__ mask, float* __restrict__ out)
{
    extern __shared__ float smf[];
    const uint32_t sb  = smem_u32(smf);
    const uint32_t QB  = sb;
    const uint32_t KB0 = sb + 32768;
    const uint32_t KB1 = sb + 49152;
    const uint32_t VB  = sb + 65536;
    const uint32_t PB  = sb + 81920;
    float* maddf = smf + 28672;

    const int t    = threadIdx.x;
    const int w    = t >> 5;
    const int lane = t & 31;
    const int g    = lane >> 2;
    const int t4   = lane & 3;
    const int i7   = lane & 7;
    const int tq   = lane >> 3;
    const int g4   = g << 2;
    const int q0   = blockIdx.x * 128;
    const int h    = blockIdx.y;
    const int b    = blockIdx.z;
    const int m0   = w * 32;

    const float BSC = ALPHA * LOG2E / (float)S_LEN;

    // ldmatrix per-lane row bases (bytes; 256B rows)
    const uint32_t laneA = (uint32_t)(m0 + ((tq & 1) << 3) + i7) * 256;   // Q, P
    const uint32_t laneB = (uint32_t)(((tq & 2) << 2) + i7) * 256;        // K, V^T

    // prologue: Q (16 cp16/thr) + K tile 0 (8 cp16/thr), one group
#pragma unroll
    for (int i = 0; i < 16; i++) {
        int idx = i * 128 + t;
        int row = idx >> 4;
        int wd  = idx & 15;
        cp16(QB + (uint32_t)(row * 256 + ((wd ^ (row & 7)) << 4)),
             &g_Q[((size_t)(b * S_LEN + q0 + row)) * E_DIM + h * D_HEAD + wd * 4]);
    }
#pragma unroll
    for (int i = 0; i < 8; i++) {
        int idx = i * 128 + t;
        int row = idx >> 4;
        int wd  = idx & 15;
        cp16(KB0 + (uint32_t)(row * 256 + ((wd ^ (row & 7)) << 4)),
             &g_K[((size_t)(b * S_LEN + row)) * E_DIM + h * D_HEAD + wd * 4]);
    }
    cp_commit();

    float o[2][8][4];
#pragma unroll
    for (int mf = 0; mf < 2; mf++)
#pragma unroll
        for (int nf = 0; nf < 8; nf++)
#pragma unroll
            for (int r = 0; r < 4; r++) o[mf][nf][r] = 0.0f;

    // per-thread partial row sums (reduced across quad once at the end)
    float lp[2][2] = {{0.0f, 0.0f}, {0.0f, 0.0f}};
    float tgt[2][2];
#pragma unroll
    for (int mf = 0; mf < 2; mf++) {
        tgt[mf][0] = (float)(S_LEN - 1 - (q0 + m0 + mf * 16 + g));
        tgt[mf][1] = (float)(S_LEN - 1 - (q0 + m0 + mf * 16 + 8 + g));
    }

    for (int kt = 0; kt < 32; kt++) {
        const int k0g = kt * 64;
        const uint32_t KB = (kt & 1) ? KB1 : KB0;

        // 1. wait K(kt) (and Q on kt=0)
        cp_wait0();
        // 2. mask additive, double-buffered
        if (t < 64)
            maddf[(kt & 1) * 64 + t] = (mask[b * S_LEN + k0g + t] != 0u) ? -1e30f : 0.0f;
        // 3. all warps finished previous tile; K(kt) visible
        __syncthreads();
        // 4. issue V^T(kt): rows = d (64), cols = s (64 keys)
#pragma unroll
        for (int i = 0; i < 8; i++) {
            int idx = i * 128 + t;
            int row = idx >> 4;     // d within head
            int wd  = idx & 15;     // s word
            cp16(VB + (uint32_t)(row * 256 + ((wd ^ (row & 7)) << 4)),
                 &g_V[((size_t)(b * 1024 + h * D_HEAD + row)) * S_LEN + k0g + wd * 4]);
        }
        cp_commit();

        // 5. S = Q @ K^T (exp2 domain; scale folded into Q)
        float sc[2][8][4];
#pragma unroll
        for (int mf = 0; mf < 2; mf++)
#pragma unroll
            for (int nf = 0; nf < 8; nf++)
#pragma unroll
                for (int r = 0; r < 4; r++) sc[mf][nf][r] = 0.0f;

#pragma unroll
        for (int ks = 0; ks < 8; ks++) {
            const uint32_t cwA = (uint32_t)(((2 * ks + (tq >> 1)) ^ i7) << 4);
            const uint32_t cwB = (uint32_t)(((2 * ks + (tq & 1)) ^ i7) << 4);
            uint32_t a0v[4], a1v[4];
            LDSM4(a0v, QB + laneA + cwA);
            LDSM4(a1v, QB + laneA + 4096 + cwA);
            uint32_t bv[16];
#pragma unroll
            for (int np = 0; np < 4; np++)
                LDSM4(&bv[np * 4], KB + laneB + np * 4096 + cwB);
#pragma unroll
            for (int nf = 0; nf < 8; nf++) {
                uint32_t b0 = bv[(nf >> 1) * 4 + (nf & 1) * 2];
                uint32_t b1 = bv[(nf >> 1) * 4 + (nf & 1) * 2 + 1];
                mma4(sc[0][nf], a0v, b0, b1);
                mma4(sc[1][nf], a1v, b0, b1);
            }
        }

        // 6. prefetch K(kt+1)
        if (kt < 31) {
            const uint32_t KBn = (kt & 1) ? KB0 : KB1;
#pragma unroll
            for (int i = 0; i < 8; i++) {
                int idx = i * 128 + t;
                int row = idx >> 4;
                int wd  = idx & 15;
                cp16(KBn + (uint32_t)(row * 256 + ((wd ^ (row & 7)) << 4)),
                     &g_K[((size_t)(b * S_LEN + k0g + 64 + row)) * E_DIM + h * D_HEAD + wd * 4]);
            }
            cp_commit();
        }

        // 7. bias + mask + p = ex2(s); partial sums; P -> smem (no max needed)
        const float* md = maddf + (kt & 1) * 64;
#pragma unroll
        for (int mf = 0; mf < 2; mf++) {
            int r = m0 + mf * 16 + g;
            float s0 = 0.0f, s1 = 0.0f;
#pragma unroll
            for (int nf = 0; nf < 8; nf++) {
                int jc = nf * 8 + 2 * t4;
                float jk0 = (float)(k0g + jc);
                float ma0 = md[jc], ma1 = md[jc + 1];
                float p0 = ex2(sc[mf][nf][0] - BSC * fabsf(jk0 - tgt[mf][0]) + ma0);
                float p1 = ex2(sc[mf][nf][1] - BSC * fabsf(jk0 + 1.0f - tgt[mf][0]) + ma1);
                float p2 = ex2(sc[mf][nf][2] - BSC * fabsf(jk0 - tgt[mf][1]) + ma0);
                float p3 = ex2(sc[mf][nf][3] - BSC * fabsf(jk0 + 1.0f - tgt[mf][1]) + ma1);
                s0 += p0 + p1;
                s1 += p2 + p3;
                int colx = (nf * 8 + 2 * t4) ^ g4;
                *(float2*)&smf[20480 + r * 64 + colx]       = make_float2(to_tf32(p0), to_tf32(p1));
                *(float2*)&smf[20480 + (r + 8) * 64 + colx] = make_float2(to_tf32(p2), to_tf32(p3));
            }
            lp[mf][0] += s0;
            lp[mf][1] += s1;
        }
        __syncwarp();   // P stores visible to ldmatrix cross-lane

        // 8. wait V(kt) [K(kt+1) may stay pending], then make visible
        if (kt < 31) cp_wait1(); else cp_wait0();
        __syncthreads();

        // 9. O += P @ V  (V^T in smem: rows d, cols s -> same B frag as K)
#pragma unroll
        for (int ks = 0; ks < 8; ks++) {
            const uint32_t cwA = (uint32_t)(((2 * ks + (tq >> 1)) ^ i7) << 4);
            const uint32_t cwB = (uint32_t)(((2 * ks + (tq & 1)) ^ i7) << 4);
            uint32_t p0v[4], p1v[4];
            LDSM4(p0v, PB + laneA + cwA);
            LDSM4(p1v, PB + laneA + 4096 + cwA);
            uint32_t bv[16];
#pragma unroll
            for (int np = 0; np < 4; np++)
                LDSM4(&bv[np * 4], VB + laneB + np * 4096 + cwB);
#pragma unroll
            for (int nf = 0; nf < 8; nf++) {
                uint32_t b0 = bv[(nf >> 1) * 4 + (nf & 1) * 2];
                uint32_t b1 = bv[(nf >> 1) * 4 + (nf & 1) * 2 + 1];
                mma4(o[0][nf], p0v, b0, b1);
                mma4(o[1][nf], p1v, b0, b1);
            }
        }
        __syncwarp();
    }

    // ---- final row-sum reduction (once), normalize, write tf32 ----
#pragma unroll
    for (int mf = 0; mf < 2; mf++) {
        float l0 = lp[mf][0];
        float l1 = lp[mf][1];
        l0 += __shfl_xor_sync(0xffffffffu, l0, 1);
        l0 += __shfl_xor_sync(0xffffffffu, l0, 2);
        l1 += __shfl_xor_sync(0xffffffffu, l1, 1);
        l1 += __shfl_xor_sync(0xffffffffu, l1, 2);
        float inv0 = 1.0f / l0;
        float inv1 = 1.0f / l1;
        size_t r0 = ((size_t)(b * S_LEN + q0 + m0 + mf * 16 + g)) * E_DIM + h * D_HEAD;
        size_t r1 = r0 + 8 * E_DIM;
#pragma unroll
        for (int nf = 0; nf < 8; nf++) {
            int col = nf * 8 + 2 * t4;
            *(float2*)&out[r0 + col] =
                make_float2(to_tf32(o[mf][nf][0] * inv0), to_tf32(o[mf][nf][1] * inv0));
            *(float2*)&out[r1 + col] =
                make_float2(to_tf32(o[mf][nf][2] * inv1), to_tf32(o[mf][nf][3] * inv1));
        }
    }
}

// ---------------------------------------------------------------------------
extern "C" void kernel_launch(void* const* d_in, const int* in_sizes, int n_in,
                              void* d_out, int out_size)
{
    const float* x    = (const float*)d_in[0];
    const float* Wq   = (const float*)d_in[1];
    const float* Wk   = (const float*)d_in[2];
    const float* Wv   = (const float*)d_in[3];
    const float* Wo   = (const float*)d_in[4];
    const unsigned int* mask = (const unsigned int*)d_in[5];
    float* out = (float*)d_out;

    float *xp, *wqp, *wkp, *wvp, *wop, *qp, *kp, *vp, *ap;
    cudaGetSymbolAddress((void**)&xp,  g_X);
    cudaGetSymbolAddress((void**)&wqp, g_Wq);
    cudaGetSymbolAddress((void**)&wkp, g_Wk);
    cudaGetSymbolAddress((void**)&wvp, g_Wv);
    cudaGetSymbolAddress((void**)&wop, g_Wo);
    cudaGetSymbolAddress((void**)&qp,  g_Q);
    cudaGetSymbolAddress((void**)&kp,  g_K);
    cudaGetSymbolAddress((void**)&vp,  g_V);
    cudaGetSymbolAddress((void**)&ap,  g_A);

    cudaFuncSetAttribute(gemm_tc, cudaFuncAttributeMaxDynamicSharedMemorySize, GEMM_SMEM);
    cudaFuncSetAttribute(attn_tc, cudaFuncAttributeMaxDynamicSharedMemorySize, ATT_SMEM);

    // 1. pre-convert inputs to tf32 (Wq scaled by 0.125*log2e)
    cvt_kernel<<<dim3(512, 1, 5), 256>>>((const float4*)x, (const float4*)Wq,
                                         (const float4*)Wk, (const float4*)Wv,
                                         (const float4*)Wo);

    // 2. fused QKV projections (V written transposed)
    gemm_tc<<<dim3(GN / 128, GM / 128, 3), 128, GEMM_SMEM>>>(
        xp, wqp, wkp, wvp, qp, kp, vp, 1);

    // 3. attention (128 threads / 4 warps, no-max softmax)
    attn_tc<<<dim3(S_LEN / 128, H_NUM, B_SZ), 128, ATT_SMEM>>>(mask, ap);

    // 4. output projection (fp32 out)
    gemm_tc<<<dim3(GN / 128, GM / 128, 1), 128, GEMM_SMEM>>>(
        ap, wop, wop, wop, out, out, out, 0);
}

// round 9
// speedup vs baseline: 1.6594x; 1.4440x over previous
#include <cuda_runtime.h>
#include <cuda_fp16.h>
#include <cstdint>
#include <math.h>

// Problem constants
#define B_SZ   2
#define S_LEN  2048
#define E_DIM  1024
#define H_NUM  16
#define D_HEAD 64
#define ALPHA  0.5f
#define LOG2E  1.4426950408889634f

#define GM 4096
#define GN 1024
#define GK 1024

// Scratch (device globals — allocation-free), all fp16 now
__device__ __half g_X [GM * GK];         // x
__device__ __half g_Wq[GN * GK];         // Wq * 0.125*log2e
__device__ __half g_Wk[GN * GK];
__device__ __half g_Wv[GN * GK];
__device__ __half g_Wo[GN * GK];
__device__ __half g_Q [GM * GN];         // pre-scaled, [b*S+s][h*64+d]
__device__ __half g_K [GM * GN];         // [b*S+s][h*64+d]
__device__ __half g_V [GM * GN];         // TRANSPOSED: [(b*1024 + h*64+d)][s]
__device__ __half g_A [GM * GN];         // attention out

// ---------------------------------------------------------------------------
// Helpers
// ---------------------------------------------------------------------------
static __device__ __forceinline__ uint32_t smem_u32(const void* p) {
    uint32_t a;
    asm("{ .reg .u64 t; cvta.to.shared.u64 t, %1; cvt.u32.u64 %0, t; }" : "=r"(a) : "l"(p));
    return a;
}
static __device__ __forceinline__ float ex2(float x) {
    float y;
    asm("ex2.approx.f32 %0, %1;" : "=f"(y) : "f"(x));
    return y;
}
static __device__ __forceinline__ void cp16(uint32_t dst, const void* src) {
    asm volatile("cp.async.cg.shared.global [%0], [%1], 16;" :: "r"(dst), "l"(src));
}
static __device__ __forceinline__ void cp_commit() {
    asm volatile("cp.async.commit_group;" ::: "memory");
}
static __device__ __forceinline__ void cp_wait0() {
    asm volatile("cp.async.wait_group 0;" ::: "memory");
}
static __device__ __forceinline__ void cp_wait1() {
    asm volatile("cp.async.wait_group 1;" ::: "memory");
}
#define LDSM4(R, ADDR)                                                        \
    asm volatile("ldmatrix.sync.aligned.m8n8.x4.shared.b16 {%0,%1,%2,%3}, [%4];" \
        : "=r"((R)[0]), "=r"((R)[1]), "=r"((R)[2]), "=r"((R)[3]) : "r"(ADDR))

// D += A(16x16) @ B(16x8), fp16 inputs, f32 accumulate
static __device__ __forceinline__ void mma8(float* d, const uint32_t* a,
                                            uint32_t b0, uint32_t b1) {
    asm volatile(
        "mma.sync.aligned.m16n8k16.row.col.f32.f16.f16.f32 "
        "{%0,%1,%2,%3}, {%4,%5,%6,%7}, {%8,%9}, {%0,%1,%2,%3};"
        : "+f"(d[0]), "+f"(d[1]), "+f"(d[2]), "+f"(d[3])
        : "r"(a[0]), "r"(a[1]), "r"(a[2]), "r"(a[3]), "r"(b0), "r"(b1));
}

// ---------------------------------------------------------------------------
// Pre-convert inputs to FP16 (scale folded for Wq)
// ---------------------------------------------------------------------------
__global__ __launch_bounds__(256)
void cvt_kernel(const float4* __restrict__ x,  const float4* __restrict__ wq,
                const float4* __restrict__ wk, const float4* __restrict__ wv,
                const float4* __restrict__ wo)
{
    const int z = blockIdx.z;
    const float4* src;
    __half2* dst;
    int n4;
    float s = 1.0f;
    switch (z) {
        case 0: src = x;  dst = (__half2*)g_X;  n4 = GM * GK / 4; break;
        case 1: src = wq; dst = (__half2*)g_Wq; n4 = GN * GK / 4; s = 0.125f * LOG2E; break;
        case 2: src = wk; dst = (__half2*)g_Wk; n4 = GN * GK / 4; break;
        case 3: src = wv; dst = (__half2*)g_Wv; n4 = GN * GK / 4; break;
        default: src = wo; dst = (__half2*)g_Wo; n4 = GN * GK / 4; break;
    }
    for (int i = blockIdx.x * 256 + threadIdx.x; i < n4; i += gridDim.x * 256) {
        float4 v = src[i];
        dst[2 * i]     = __floats2half2_rn(v.x * s, v.y * s);
        dst[2 * i + 1] = __floats2half2_rn(v.z * s, v.w * s);
    }
}

// ---------------------------------------------------------------------------
// FP16 GEMM: C = A[M,K] @ W[N,K]^T (fp16 inputs, f32 accum).
// CTA 128x128, 128 threads (4 warps, 2x2), warp tile 64x64, K-chunk 64 halves
// (128B rows), 3-stage cp.async pipeline, ldmatrix, XOR-swizzled smem.
// cvt_out=1: fp16 outputs; z==2 additionally stores V TRANSPOSED.
// cvt_out=0: f32 output.
// ---------------------------------------------------------------------------
#define GEMM_SMEM (3 * 32768)

__global__ __launch_bounds__(128, 2)
void gemm_tc(const __half* __restrict__ A,
             const __half* __restrict__ W0, const __half* __restrict__ W1,
             const __half* __restrict__ W2,
             void* __restrict__ C0, void* __restrict__ C1, void* __restrict__ C2,
             int cvt_out)
{
    extern __shared__ char smc[];
    const uint32_t sb = smem_u32(smc);

    const __half* W = (blockIdx.z == 0) ? W0 : (blockIdx.z == 1) ? W1 : W2;
    void*         C = (blockIdx.z == 0) ? C0 : (blockIdx.z == 1) ? C1 : C2;

    const int t    = threadIdx.x;
    const int w    = t >> 5;
    const int lane = t & 31;
    const int g    = lane >> 2;
    const int t4   = lane & 3;
    const int i7   = lane & 7;
    const int tq   = lane >> 3;
    const int m0   = (w >> 1) * 64;
    const int n0   = (w & 1) * 64;
    const int bm   = blockIdx.y * 128;
    const int bn   = blockIdx.x * 128;

    const uint32_t laneA = (uint32_t)(m0 + ((tq & 1) << 3) + i7) * 128;
    const uint32_t laneB = (uint32_t)(n0 + ((tq & 2) << 2) + i7) * 128;

    float acc[4][8][4];
#pragma unroll
    for (int mf = 0; mf < 4; mf++)
#pragma unroll
        for (int nf = 0; nf < 8; nf++)
#pragma unroll
            for (int r = 0; r < 4; r++) acc[mf][nf][r] = 0.0f;

#define GEMM_ISSUE(CH) do {                                                     \
        const int _k0 = (CH) * 64;                                              \
        const uint32_t _sa = sb + ((CH) % 3) * 32768;                           \
        _Pragma("unroll")                                                       \
        for (int _i = 0; _i < 8; _i++) {                                        \
            int _idx = _i * 128 + t;                                            \
            int _row = _idx >> 3;                                               \
            int _wd  = _idx & 7;                                                \
            uint32_t _o = (uint32_t)(_row * 128 + (((_wd) ^ (_row & 7)) << 4)); \
            cp16(_sa + _o,         &A[(size_t)(bm + _row) * GK + _k0 + _wd * 8]); \
            cp16(_sa + 16384 + _o, &W[(size_t)(bn + _row) * GK + _k0 + _wd * 8]); \
        }                                                                       \
        cp_commit();                                                            \
    } while (0)

    GEMM_ISSUE(0);
    GEMM_ISSUE(1);

    for (int ch = 0; ch < 16; ch++) {
        if (ch < 15) cp_wait1(); else cp_wait0();
        __syncthreads();
        if (ch + 2 < 16) GEMM_ISSUE(ch + 2);

        const uint32_t stage = sb + (ch % 3) * 32768;
#pragma unroll
        for (int ks = 0; ks < 4; ks++) {
            const uint32_t cwA = (uint32_t)(((2 * ks + (tq >> 1)) ^ i7) << 4);
            const uint32_t cwB = (uint32_t)(((2 * ks + (tq & 1)) ^ i7) << 4);
            uint32_t av[4][4];
#pragma unroll
            for (int mf = 0; mf < 4; mf++)
                LDSM4(av[mf], stage + laneA + mf * 2048 + cwA);
            uint32_t bv[16];
#pragma unroll
            for (int np = 0; np < 4; np++)
                LDSM4(&bv[np * 4], stage + 16384 + laneB + np * 2048 + cwB);
#pragma unroll
            for (int nf = 0; nf < 8; nf++) {
                uint32_t b0 = bv[(nf >> 1) * 4 + (nf & 1) * 2];
                uint32_t b1 = bv[(nf >> 1) * 4 + (nf & 1) * 2 + 1];
#pragma unroll
                for (int mf = 0; mf < 4; mf++)
                    mma8(acc[mf][nf], av[mf], b0, b1);
            }
        }
    }

    // epilogue
    if (cvt_out && blockIdx.z == 2) {
        // V: transposed fp16 store -> C[(b*1024 + n)][s]
        __half* Ch = (__half*)C;
        const int bb = bm >> 11;
#pragma unroll
        for (int mf = 0; mf < 4; mf++) {
            int row = bm + m0 + mf * 16 + g;
            int s   = row & (S_LEN - 1);
#pragma unroll
            for (int nf = 0; nf < 8; nf++) {
                int col = bn + n0 + nf * 8 + 2 * t4;
                size_t base = ((size_t)(bb * 1024 + col)) * S_LEN + s;
                Ch[base]             = __float2half_rn(acc[mf][nf][0]);
                Ch[base + S_LEN]     = __float2half_rn(acc[mf][nf][1]);
                Ch[base + 8]         = __float2half_rn(acc[mf][nf][2]);
                Ch[base + S_LEN + 8] = __float2half_rn(acc[mf][nf][3]);
            }
        }
    } else if (cvt_out) {
        __half* Ch = (__half*)C;
#pragma unroll
        for (int mf = 0; mf < 4; mf++) {
            int row = bm + m0 + mf * 16 + g;
#pragma unroll
            for (int nf = 0; nf < 8; nf++) {
                int col = bn + n0 + nf * 8 + 2 * t4;
                *(__half2*)&Ch[(size_t)row * GN + col] =
                    __floats2half2_rn(acc[mf][nf][0], acc[mf][nf][1]);
                *(__half2*)&Ch[(size_t)(row + 8) * GN + col] =
                    __floats2half2_rn(acc[mf][nf][2], acc[mf][nf][3]);
            }
        }
    } else {
        float* Cf = (float*)C;
#pragma unroll
        for (int mf = 0; mf < 4; mf++) {
            int row = bm + m0 + mf * 16 + g;
#pragma unroll
            for (int nf = 0; nf < 8; nf++) {
                int col = bn + n0 + nf * 8 + 2 * t4;
                *(float2*)&Cf[(size_t)row * GN + col] =
                    make_float2(acc[mf][nf][0], acc[mf][nf][1]);
                *(float2*)&Cf[(size_t)(row + 8) * GN + col] =
                    make_float2(acc[mf][nf][2], acc[mf][nf][3]);
            }
        }
    }
#undef GEMM_ISSUE
}

// ---------------------------------------------------------------------------
// FP16 flash attention, exp2-domain softmax without running max (scores
// bounded; masked -> ex2(-1e30)=0 exactly).  128 threads (4 warps);
// CTA = 128 queries of one (b,h); warp = 32 q-rows.  K double-buffered +
// pipelined; V^T via ldmatrix.  All tiles 128-byte rows (64 halves).
// SMEM bytes: Q @0 (16K), K0 @16384 (8K), K1 @24576 (8K), V @32768 (8K),
//             P @40960 (16K), madd @57344 (512).  Total 57,856 B -> 3 CTAs/SM.
// ---------------------------------------------------------------------------
#define ATT_SMEM 57856

__global__ __launch_bounds__(128, 3)
void attn_tc(const unsigned int* __restrict__ mask, __half* __restrict__ out)
{
    extern __shared__ char smc[];
    const uint32_t sb  = smem_u32(smc);
    const uint32_t QB  = sb;
    const uint32_t KB0 = sb + 16384;
    const uint32_t KB1 = sb + 24576;
    const uint32_t VB  = sb + 32768;
    const uint32_t PB  = sb + 40960;
    float* maddf = (float*)(smc + 57344);

    const int t    = threadIdx.x;
    const int w    = t >> 5;
    const int lane = t & 31;
    const int g    = lane >> 2;
    const int t4   = lane & 3;
    const int i7   = lane & 7;
    const int tq   = lane >> 3;
    const int q0   = blockIdx.x * 128;
    const int h    = blockIdx.y;
    const int b    = blockIdx.z;
    const int m0   = w * 32;

    const float BSC = ALPHA * LOG2E / (float)S_LEN;

    // ldmatrix per-lane row bases (bytes; 128B rows)
    const uint32_t laneA = (uint32_t)(m0 + ((tq & 1) << 3) + i7) * 128;   // Q, P
    const uint32_t laneB = (uint32_t)(((tq & 2) << 2) + i7) * 128;        // K, V^T

    // prologue: Q (8 cp16/thr) + K tile 0 (4 cp16/thr), one group
#pragma unroll
    for (int i = 0; i < 8; i++) {
        int idx = i * 128 + t;
        int row = idx >> 3;
        int wd  = idx & 7;
        cp16(QB + (uint32_t)(row * 128 + ((wd ^ (row & 7)) << 4)),
             &g_Q[((size_t)(b * S_LEN + q0 + row)) * E_DIM + h * D_HEAD + wd * 8]);
    }
#pragma unroll
    for (int i = 0; i < 4; i++) {
        int idx = i * 128 + t;
        int row = idx >> 3;
        int wd  = idx & 7;
        cp16(KB0 + (uint32_t)(row * 128 + ((wd ^ (row & 7)) << 4)),
             &g_K[((size_t)(b * S_LEN + row)) * E_DIM + h * D_HEAD + wd * 8]);
    }
    cp_commit();

    float o[2][8][4];
#pragma unroll
    for (int mf = 0; mf < 2; mf++)
#pragma unroll
        for (int nf = 0; nf < 8; nf++)
#pragma unroll
            for (int r = 0; r < 4; r++) o[mf][nf][r] = 0.0f;

    float lp[2][2] = {{0.0f, 0.0f}, {0.0f, 0.0f}};
    float tgt[2][2];
#pragma unroll
    for (int mf = 0; mf < 2; mf++) {
        tgt[mf][0] = (float)(S_LEN - 1 - (q0 + m0 + mf * 16 + g));
        tgt[mf][1] = (float)(S_LEN - 1 - (q0 + m0 + mf * 16 + 8 + g));
    }

    for (int kt = 0; kt < 32; kt++) {
        const int k0g = kt * 64;
        const uint32_t KB = (kt & 1) ? KB1 : KB0;

        // 1. wait K(kt) (and Q on kt=0)
        cp_wait0();
        // 2. mask additive, double-buffered
        if (t < 64)
            maddf[(kt & 1) * 64 + t] = (mask[b * S_LEN + k0g + t] != 0u) ? -1e30f : 0.0f;
        // 3. all warps finished previous tile; K(kt) visible
        __syncthreads();
        // 4. issue V^T(kt): rows = d (64), cols = s (64 keys)
#pragma unroll
        for (int i = 0; i < 4; i++) {
            int idx = i * 128 + t;
            int row = idx >> 3;     // d within head
            int wd  = idx & 7;      // s word (8 halves)
            cp16(VB + (uint32_t)(row * 128 + ((wd ^ (row & 7)) << 4)),
                 &g_V[((size_t)(b * 1024 + h * D_HEAD + row)) * S_LEN + k0g + wd * 8]);
        }
        cp_commit();

        // 5. S = Q @ K^T (exp2 domain; scale folded into Q)
        float sc[2][8][4];
#pragma unroll
        for (int mf = 0; mf < 2; mf++)
#pragma unroll
            for (int nf = 0; nf < 8; nf++)
#pragma unroll
                for (int r = 0; r < 4; r++) sc[mf][nf][r] = 0.0f;

#pragma unroll
        for (int ks = 0; ks < 4; ks++) {
            const uint32_t cwA = (uint32_t)(((2 * ks + (tq >> 1)) ^ i7) << 4);
            const uint32_t cwB = (uint32_t)(((2 * ks + (tq & 1)) ^ i7) << 4);
            uint32_t a0v[4], a1v[4];
            LDSM4(a0v, QB + laneA + cwA);
            LDSM4(a1v, QB + laneA + 2048 + cwA);
            uint32_t bv[16];
#pragma unroll
            for (int np = 0; np < 4; np++)
                LDSM4(&bv[np * 4], KB + laneB + np * 2048 + cwB);
#pragma unroll
            for (int nf = 0; nf < 8; nf++) {
                uint32_t b0 = bv[(nf >> 1) * 4 + (nf & 1) * 2];
                uint32_t b1 = bv[(nf >> 1) * 4 + (nf & 1) * 2 + 1];
                mma8(sc[0][nf], a0v, b0, b1);
                mma8(sc[1][nf], a1v, b0, b1);
            }
        }

        // 6. prefetch K(kt+1)
        if (kt < 31) {
            const uint32_t KBn = (kt & 1) ? KB0 : KB1;
#pragma unroll
            for (int i = 0; i < 4; i++) {
                int idx = i * 128 + t;
                int row = idx >> 3;
                int wd  = idx & 7;
                cp16(KBn + (uint32_t)(row * 128 + ((wd ^ (row & 7)) << 4)),
                     &g_K[((size_t)(b * S_LEN + k0g + 64 + row)) * E_DIM + h * D_HEAD + wd * 8]);
            }
            cp_commit();
        }

        // 7. bias + mask + p = ex2(s); partial sums; P -> smem (fp16 pairs)
        const float* md = maddf + (kt & 1) * 64;
#pragma unroll
        for (int mf = 0; mf < 2; mf++) {
            int r = m0 + mf * 16 + g;
            float s0 = 0.0f, s1 = 0.0f;
#pragma unroll
            for (int nf = 0; nf < 8; nf++) {
                int jc = nf * 8 + 2 * t4;
                float jk0 = (float)(k0g + jc);
                float ma0 = md[jc], ma1 = md[jc + 1];
                float p0 = ex2(sc[mf][nf][0] - BSC * fabsf(jk0 - tgt[mf][0]) + ma0);
                float p1 = ex2(sc[mf][nf][1] - BSC * fabsf(jk0 + 1.0f - tgt[mf][0]) + ma1);
                float p2 = ex2(sc[mf][nf][2] - BSC * fabsf(jk0 - tgt[mf][1]) + ma0);
                float p3 = ex2(sc[mf][nf][3] - BSC * fabsf(jk0 + 1.0f - tgt[mf][1]) + ma1);
                s0 += p0 + p1;
                s1 += p2 + p3;
                // P store: row r (and r+8), 16B word nf (^ row swizzle), +4*t4
                uint32_t pb = (uint32_t)(PB - sb) + (uint32_t)r * 128
                            + ((uint32_t)(nf ^ (r & 7)) << 4) + 4 * t4;
                *(__half2*)(smc + pb)        = __floats2half2_rn(p0, p1);
                *(__half2*)(smc + pb + 1024) = __floats2half2_rn(p2, p3);
            }
            lp[mf][0] += s0;
            lp[mf][1] += s1;
        }
        __syncwarp();   // P stores visible to ldmatrix cross-lane

        // 8. wait V(kt) [K(kt+1) may stay pending], then make visible
        if (kt < 31) cp_wait1(); else cp_wait0();
        __syncthreads();

        // 9. O += P @ V  (V^T in smem: rows d, cols s -> same B frag as K)
#pragma unroll
        for (int ks = 0; ks < 4; ks++) {
            const uint32_t cwA = (uint32_t)(((2 * ks + (tq >> 1)) ^ i7) << 4);
            const uint32_t cwB = (uint32_t)(((2 * ks + (tq & 1)) ^ i7) << 4);
            uint32_t p0v[4], p1v[4];
            LDSM4(p0v, PB + laneA + cwA);
            LDSM4(p1v, PB + laneA + 2048 + cwA);
            uint32_t bv[16];
#pragma unroll
            for (int np = 0; np < 4; np++)
                LDSM4(&bv[np * 4], VB + laneB + np * 2048 + cwB);
#pragma unroll
            for (int nf = 0; nf < 8; nf++) {
                uint32_t b0 = bv[(nf >> 1) * 4 + (nf & 1) * 2];
                uint32_t b1 = bv[(nf >> 1) * 4 + (nf & 1) * 2 + 1];
                mma8(o[0][nf], p0v, b0, b1);
                mma8(o[1][nf], p1v, b0, b1);
            }
        }
        __syncwarp();
    }

    // ---- final row-sum reduction (once), normalize, write fp16 ----
#pragma unroll
    for (int mf = 0; mf < 2; mf++) {
        float l0 = lp[mf][0];
        float l1 = lp[mf][1];
        l0 += __shfl_xor_sync(0xffffffffu, l0, 1);
        l0 += __shfl_xor_sync(0xffffffffu, l0, 2);
        l1 += __shfl_xor_sync(0xffffffffu, l1, 1);
        l1 += __shfl_xor_sync(0xffffffffu, l1, 2);
        float inv0 = 1.0f / l0;
        float inv1 = 1.0f / l1;
        size_t r0 = ((size_t)(b * S_LEN + q0 + m0 + mf * 16 + g)) * E_DIM + h * D_HEAD;
        size_t r1 = r0 + 8 * E_DIM;
#pragma unroll
        for (int nf = 0; nf < 8; nf++) {
            int col = nf * 8 + 2 * t4;
            *(__half2*)&out[r0 + col] =
                __floats2half2_rn(o[mf][nf][0] * inv0, o[mf][nf][1] * inv0);
            *(__half2*)&out[r1 + col] =
                __floats2half2_rn(o[mf][nf][2] * inv1, o[mf][nf][3] * inv1);
        }
    }
}

// ---------------------------------------------------------------------------
extern "C" void kernel_launch(void* const* d_in, const int* in_sizes, int n_in,
                              void* d_out, int out_size)
{
    const float* x    = (const float*)d_in[0];
    const float* Wq   = (const float*)d_in[1];
    const float* Wk   = (const float*)d_in[2];
    const float* Wv   = (const float*)d_in[3];
    const float* Wo   = (const float*)d_in[4];
    const unsigned int* mask = (const unsigned int*)d_in[5];
    float* out = (float*)d_out;

    __half *xp, *wqp, *wkp, *wvp, *wop, *qp, *kp, *vp, *ap;
    cudaGetSymbolAddress((void**)&xp,  g_X);
    cudaGetSymbolAddress((void**)&wqp, g_Wq);
    cudaGetSymbolAddress((void**)&wkp, g_Wk);
    cudaGetSymbolAddress((void**)&wvp, g_Wv);
    cudaGetSymbolAddress((void**)&wop, g_Wo);
    cudaGetSymbolAddress((void**)&qp,  g_Q);
    cudaGetSymbolAddress((void**)&kp,  g_K);
    cudaGetSymbolAddress((void**)&vp,  g_V);
    cudaGetSymbolAddress((void**)&ap,  g_A);

    cudaFuncSetAttribute(gemm_tc, cudaFuncAttributeMaxDynamicSharedMemorySize, GEMM_SMEM);
    cudaFuncSetAttribute(attn_tc, cudaFuncAttributeMaxDynamicSharedMemorySize, ATT_SMEM);

    // 1. pre-convert inputs to fp16 (Wq scaled by 0.125*log2e)
    cvt_kernel<<<dim3(512, 1, 5), 256>>>((const float4*)x, (const float4*)Wq,
                                         (const float4*)Wk, (const float4*)Wv,
                                         (const float4*)Wo);

    // 2. fused QKV projections (V written transposed)
    gemm_tc<<<dim3(GN / 128, GM / 128, 3), 128, GEMM_SMEM>>>(
        xp, wqp, wkp, wvp, qp, kp, vp, 1);

    // 3. attention (128 threads / 4 warps, fp16, no-max softmax)
    attn_tc<<<dim3(S_LEN / 128, H_NUM, B_SZ), 128, ATT_SMEM>>>(mask, ap);

    // 4. output projection (fp32 out)
    gemm_tc<<<dim3(GN / 128, GM / 128, 1), 128, GEMM_SMEM>>>(
        ap, wop, wop, wop, out, out, out, 0);
}

// round 10
// speedup vs baseline: 1.7383x; 1.0476x over previous
#include <cuda_runtime.h>
#include <cuda_fp16.h>
#include <cstdint>
#include <math.h>

// Problem constants
#define B_SZ   2
#define S_LEN  2048
#define E_DIM  1024
#define H_NUM  16
#define D_HEAD 64
#define ALPHA  0.5f
#define LOG2E  1.4426950408889634f

#define GM 4096
#define GN 1024
#define GK 1024

// Scratch (device globals — allocation-free), all fp16
__device__ __half g_X [GM * GK];
__device__ __half g_Wq[GN * GK];         // Wq * 0.125*log2e
__device__ __half g_Wk[GN * GK];
__device__ __half g_Wv[GN * GK];
__device__ __half g_Wo[GN * GK];
__device__ __half g_Q [GM * GN];         // pre-scaled, [b*S+s][h*64+d]
__device__ __half g_K [GM * GN];         // [b*S+s][h*64+d]
__device__ __half g_V [GM * GN];         // TRANSPOSED: [(b*1024 + h*64+d)][s]
__device__ __half g_A [GM * GN];

// ---------------------------------------------------------------------------
// Helpers
// ---------------------------------------------------------------------------
static __device__ __forceinline__ uint32_t smem_u32(const void* p) {
    uint32_t a;
    asm("{ .reg .u64 t; cvta.to.shared.u64 t, %1; cvt.u32.u64 %0, t; }" : "=r"(a) : "l"(p));
    return a;
}
static __device__ __forceinline__ float ex2(float x) {
    float y;
    asm("ex2.approx.f32 %0, %1;" : "=f"(y) : "f"(x));
    return y;
}
static __device__ __forceinline__ void cp16(uint32_t dst, const void* src) {
    asm volatile("cp.async.cg.shared.global [%0], [%1], 16;" :: "r"(dst), "l"(src));
}
static __device__ __forceinline__ void cp_commit() {
    asm volatile("cp.async.commit_group;" ::: "memory");
}
static __device__ __forceinline__ void cp_wait0() {
    asm volatile("cp.async.wait_group 0;" ::: "memory");
}
static __device__ __forceinline__ void cp_wait1() {
    asm volatile("cp.async.wait_group 1;" ::: "memory");
}
#define LDSM4(R, ADDR)                                                        \
    asm volatile("ldmatrix.sync.aligned.m8n8.x4.shared.b16 {%0,%1,%2,%3}, [%4];" \
        : "=r"((R)[0]), "=r"((R)[1]), "=r"((R)[2]), "=r"((R)[3]) : "r"(ADDR))

// D += A(16x16) @ B(16x8), fp16 inputs, f32 accumulate
static __device__ __forceinline__ void mma8(float* d, const uint32_t* a,
                                            uint32_t b0, uint32_t b1) {
    asm volatile(
        "mma.sync.aligned.m16n8k16.row.col.f32.f16.f16.f32 "
        "{%0,%1,%2,%3}, {%4,%5,%6,%7}, {%8,%9}, {%0,%1,%2,%3};"
        : "+f"(d[0]), "+f"(d[1]), "+f"(d[2]), "+f"(d[3])
        : "r"(a[0]), "r"(a[1]), "r"(a[2]), "r"(a[3]), "r"(b0), "r"(b1));
}

// ---------------------------------------------------------------------------
// Pre-convert inputs to FP16 (scale folded for Wq)
// ---------------------------------------------------------------------------
__global__ __launch_bounds__(256)
void cvt_kernel(const float4* __restrict__ x,  const float4* __restrict__ wq,
                const float4* __restrict__ wk, const float4* __restrict__ wv,
                const float4* __restrict__ wo)
{
    const int z = blockIdx.z;
    const float4* src;
    __half2* dst;
    int n4;
    float s = 1.0f;
    switch (z) {
        case 0: src = x;  dst = (__half2*)g_X;  n4 = GM * GK / 4; break;
        case 1: src = wq; dst = (__half2*)g_Wq; n4 = GN * GK / 4; s = 0.125f * LOG2E; break;
        case 2: src = wk; dst = (__half2*)g_Wk; n4 = GN * GK / 4; break;
        case 3: src = wv; dst = (__half2*)g_Wv; n4 = GN * GK / 4; break;
        default: src = wo; dst = (__half2*)g_Wo; n4 = GN * GK / 4; break;
    }
    for (int i = blockIdx.x * 256 + threadIdx.x; i < n4; i += gridDim.x * 256) {
        float4 v = src[i];
        dst[2 * i]     = __floats2half2_rn(v.x * s, v.y * s);
        dst[2 * i + 1] = __floats2half2_rn(v.z * s, v.w * s);
    }
}

// ---------------------------------------------------------------------------
// FP16 GEMM (unchanged from round 9): C = A[M,K] @ W[N,K]^T, f32 accum.
// ---------------------------------------------------------------------------
#define GEMM_SMEM (3 * 32768)

__global__ __launch_bounds__(128, 2)
void gemm_tc(const __half* __restrict__ A,
             const __half* __restrict__ W0, const __half* __restrict__ W1,
             const __half* __restrict__ W2,
             void* __restrict__ C0, void* __restrict__ C1, void* __restrict__ C2,
             int cvt_out)
{
    extern __shared__ char smc[];
    const uint32_t sb = smem_u32(smc);

    const __half* W = (blockIdx.z == 0) ? W0 : (blockIdx.z == 1) ? W1 : W2;
    void*         C = (blockIdx.z == 0) ? C0 : (blockIdx.z == 1) ? C1 : C2;

    const int t    = threadIdx.x;
    const int w    = t >> 5;
    const int lane = t & 31;
    const int g    = lane >> 2;
    const int t4   = lane & 3;
    const int i7   = lane & 7;
    const int tq   = lane >> 3;
    const int m0   = (w >> 1) * 64;
    const int n0   = (w & 1) * 64;
    const int bm   = blockIdx.y * 128;
    const int bn   = blockIdx.x * 128;

    const uint32_t laneA = (uint32_t)(m0 + ((tq & 1) << 3) + i7) * 128;
    const uint32_t laneB = (uint32_t)(n0 + ((tq & 2) << 2) + i7) * 128;

    float acc[4][8][4];
#pragma unroll
    for (int mf = 0; mf < 4; mf++)
#pragma unroll
        for (int nf = 0; nf < 8; nf++)
#pragma unroll
            for (int r = 0; r < 4; r++) acc[mf][nf][r] = 0.0f;

#define GEMM_ISSUE(CH) do {                                                     \
        const int _k0 = (CH) * 64;                                              \
        const uint32_t _sa = sb + ((CH) % 3) * 32768;                           \
        _Pragma("unroll")                                                       \
        for (int _i = 0; _i < 8; _i++) {                                        \
            int _idx = _i * 128 + t;                                            \
            int _row = _idx >> 3;                                               \
            int _wd  = _idx & 7;                                                \
            uint32_t _o = (uint32_t)(_row * 128 + (((_wd) ^ (_row & 7)) << 4)); \
            cp16(_sa + _o,         &A[(size_t)(bm + _row) * GK + _k0 + _wd * 8]); \
            cp16(_sa + 16384 + _o, &W[(size_t)(bn + _row) * GK + _k0 + _wd * 8]); \
        }                                                                       \
        cp_commit();                                                            \
    } while (0)

    GEMM_ISSUE(0);
    GEMM_ISSUE(1);

    for (int ch = 0; ch < 16; ch++) {
        if (ch < 15) cp_wait1(); else cp_wait0();
        __syncthreads();
        if (ch + 2 < 16) GEMM_ISSUE(ch + 2);

        const uint32_t stage = sb + (ch % 3) * 32768;
#pragma unroll
        for (int ks = 0; ks < 4; ks++) {
            const uint32_t cwA = (uint32_t)(((2 * ks + (tq >> 1)) ^ i7) << 4);
            const uint32_t cwB = (uint32_t)(((2 * ks + (tq & 1)) ^ i7) << 4);
            uint32_t av[4][4];
#pragma unroll
            for (int mf = 0; mf < 4; mf++)
                LDSM4(av[mf], stage + laneA + mf * 2048 + cwA);
            uint32_t bv[16];
#pragma unroll
            for (int np = 0; np < 4; np++)
                LDSM4(&bv[np * 4], stage + 16384 + laneB + np * 2048 + cwB);
#pragma unroll
            for (int nf = 0; nf < 8; nf++) {
                uint32_t b0 = bv[(nf >> 1) * 4 + (nf & 1) * 2];
                uint32_t b1 = bv[(nf >> 1) * 4 + (nf & 1) * 2 + 1];
#pragma unroll
                for (int mf = 0; mf < 4; mf++)
                    mma8(acc[mf][nf], av[mf], b0, b1);
            }
        }
    }

    // epilogue
    if (cvt_out && blockIdx.z == 2) {
        __half* Ch = (__half*)C;
        const int bb = bm >> 11;
#pragma unroll
        for (int mf = 0; mf < 4; mf++) {
            int row = bm + m0 + mf * 16 + g;
            int s   = row & (S_LEN - 1);
#pragma unroll
            for (int nf = 0; nf < 8; nf++) {
                int col = bn + n0 + nf * 8 + 2 * t4;
                size_t base = ((size_t)(bb * 1024 + col)) * S_LEN + s;
                Ch[base]             = __float2half_rn(acc[mf][nf][0]);
                Ch[base + S_LEN]     = __float2half_rn(acc[mf][nf][1]);
                Ch[base + 8]         = __float2half_rn(acc[mf][nf][2]);
                Ch[base + S_LEN + 8] = __float2half_rn(acc[mf][nf][3]);
            }
        }
    } else if (cvt_out) {
        __half* Ch = (__half*)C;
#pragma unroll
        for (int mf = 0; mf < 4; mf++) {
            int row = bm + m0 + mf * 16 + g;
#pragma unroll
            for (int nf = 0; nf < 8; nf++) {
                int col = bn + n0 + nf * 8 + 2 * t4;
                *(__half2*)&Ch[(size_t)row * GN + col] =
                    __floats2half2_rn(acc[mf][nf][0], acc[mf][nf][1]);
                *(__half2*)&Ch[(size_t)(row + 8) * GN + col] =
                    __floats2half2_rn(acc[mf][nf][2], acc[mf][nf][3]);
            }
        }
    } else {
        float* Cf = (float*)C;
#pragma unroll
        for (int mf = 0; mf < 4; mf++) {
            int row = bm + m0 + mf * 16 + g;
#pragma unroll
            for (int nf = 0; nf < 8; nf++) {
                int col = bn + n0 + nf * 8 + 2 * t4;
                *(float2*)&Cf[(size_t)row * GN + col] =
                    make_float2(acc[mf][nf][0], acc[mf][nf][1]);
                *(float2*)&Cf[(size_t)(row + 8) * GN + col] =
                    make_float2(acc[mf][nf][2], acc[mf][nf][3]);
            }
        }
    }
#undef GEMM_ISSUE
}

// ---------------------------------------------------------------------------
// FP16 flash attention, no-max exp2 softmax, ONE barrier per tile.
// K and V both double-buffered; K/V/mask for tile t+1 issued at top of tile t.
// Softmax split by mf to cap live registers (no spill at 3 CTAs/SM).
// SMEM: Q @0 (16K), K0 @16384, K1 @24576, V0 @32768, V1 @40960 (8K each),
//       P @49152 (16K), madd @65536 (512B).  Total 66,048 B -> 3 CTAs/SM.
// ---------------------------------------------------------------------------
#define ATT_SMEM 66048

__global__ __launch_bounds__(128, 3)
void attn_tc(const unsigned int* __restrict__ mask, __half* __restrict__ out)
{
    extern __shared__ char smc[];
    const uint32_t sb  = smem_u32(smc);
    const uint32_t QB  = sb;
    const uint32_t KB0 = sb + 16384;
    const uint32_t VB0 = sb + 32768;
    const uint32_t PB  = sb + 49152;
    float* maddf = (float*)(smc + 65536);

    const int t    = threadIdx.x;
    const int w    = t >> 5;
    const int lane = t & 31;
    const int g    = lane >> 2;
    const int t4   = lane & 3;
    const int i7   = lane & 7;
    const int tq   = lane >> 3;
    const int q0   = blockIdx.x * 128;
    const int h    = blockIdx.y;
    const int b    = blockIdx.z;
    const int m0   = w * 32;

    const float BSC = ALPHA * LOG2E / (float)S_LEN;

    // ldmatrix per-lane row bases (bytes; 128B rows)
    const uint32_t laneA = (uint32_t)(m0 + ((tq & 1) << 3) + i7) * 128;   // Q, P
    const uint32_t laneB = (uint32_t)(((tq & 2) << 2) + i7) * 128;        // K, V^T

    // prologue: Q + K(0) + V(0) in one group; madd[0]
#pragma unroll
    for (int i = 0; i < 8; i++) {
        int idx = i * 128 + t;
        int row = idx >> 3;
        int wd  = idx & 7;
        cp16(QB + (uint32_t)(row * 128 + ((wd ^ (row & 7)) << 4)),
             &g_Q[((size_t)(b * S_LEN + q0 + row)) * E_DIM + h * D_HEAD + wd * 8]);
    }
#pragma unroll
    for (int i = 0; i < 4; i++) {
        int idx = i * 128 + t;
        int row = idx >> 3;
        int wd  = idx & 7;
        uint32_t so = (uint32_t)(row * 128 + ((wd ^ (row & 7)) << 4));
        cp16(KB0 + so, &g_K[((size_t)(b * S_LEN + row)) * E_DIM + h * D_HEAD + wd * 8]);
        cp16(VB0 + so, &g_V[((size_t)(b * 1024 + h * D_HEAD + row)) * S_LEN + wd * 8]);
    }
    cp_commit();
    if (t < 64)
        maddf[t] = (mask[b * S_LEN + t] != 0u) ? -1e30f : 0.0f;

    float o[2][8][4];
#pragma unroll
    for (int mf = 0; mf < 2; mf++)
#pragma unroll
        for (int nf = 0; nf < 8; nf++)
#pragma unroll
            for (int r = 0; r < 4; r++) o[mf][nf][r] = 0.0f;

    float lp[2][2] = {{0.0f, 0.0f}, {0.0f, 0.0f}};
    const float tgt00 = (float)(S_LEN - 1 - (q0 + m0 + g));

    for (int kt = 0; kt < 32; kt++) {
        const int k0g = kt * 64;
        const uint32_t KB  = KB0 + ((uint32_t)(kt & 1) << 13);
        const uint32_t VBc = VB0 + ((uint32_t)(kt & 1) << 13);

        // single sync point: K(kt), V(kt), (Q on kt=0) complete + visible;
        // also protects alt buffers and madd for overwrite.
        cp_wait0();
        __syncthreads();

        // issue K(kt+1), V(kt+1), mask(kt+1)
        if (kt < 31) {
            const uint32_t KBn = KB0 + ((uint32_t)(~kt & 1) << 13);
            const uint32_t VBn = VB0 + ((uint32_t)(~kt & 1) << 13);
#pragma unroll
            for (int i = 0; i < 4; i++) {
                int idx = i * 128 + t;
                int row = idx >> 3;
                int wd  = idx & 7;
                uint32_t so = (uint32_t)(row * 128 + ((wd ^ (row & 7)) << 4));
                cp16(KBn + so,
                     &g_K[((size_t)(b * S_LEN + k0g + 64 + row)) * E_DIM + h * D_HEAD + wd * 8]);
                cp16(VBn + so,
                     &g_V[((size_t)(b * 1024 + h * D_HEAD + row)) * S_LEN + k0g + 64 + wd * 8]);
            }
            cp_commit();
            if (t < 64)
                maddf[(~kt & 1) * 64 + t] =
                    (mask[b * S_LEN + k0g + 64 + t] != 0u) ? -1e30f : 0.0f;
        }

        const float* md = maddf + (kt & 1) * 64;

        // QK + softmax, one mf at a time (keeps sc live range at 32 regs)
#pragma unroll
        for (int mf = 0; mf < 2; mf++) {
            float sc[8][4];
#pragma unroll
            for (int nf = 0; nf < 8; nf++)
#pragma unroll
                for (int r = 0; r < 4; r++) sc[nf][r] = 0.0f;

#pragma unroll
            for (int ks = 0; ks < 4; ks++) {
                const uint32_t cwA = (uint32_t)(((2 * ks + (tq >> 1)) ^ i7) << 4);
                const uint32_t cwB = (uint32_t)(((2 * ks + (tq & 1)) ^ i7) << 4);
                uint32_t av[4];
                LDSM4(av, QB + laneA + mf * 2048 + cwA);
                uint32_t bv[16];
#pragma unroll
                for (int np = 0; np < 4; np++)
                    LDSM4(&bv[np * 4], KB + laneB + np * 2048 + cwB);
#pragma unroll
                for (int nf = 0; nf < 8; nf++) {
                    uint32_t b0 = bv[(nf >> 1) * 4 + (nf & 1) * 2];
                    uint32_t b1 = bv[(nf >> 1) * 4 + (nf & 1) * 2 + 1];
                    mma8(sc[nf], av, b0, b1);
                }
            }

            // bias + mask + p = ex2(s); partial sums; P -> smem (fp16 pairs)
            const float tgtA = tgt00 - (float)(mf * 16);
            const float tgtB = tgtA - 8.0f;
            const int r = m0 + mf * 16 + g;
            float s0 = 0.0f, s1 = 0.0f;
#pragma unroll
            for (int nf = 0; nf < 8; nf++) {
                int jc = nf * 8 + 2 * t4;
                float jk0 = (float)(k0g + jc);
                float ma0 = md[jc], ma1 = md[jc + 1];
                float p0 = ex2(sc[nf][0] - BSC * fabsf(jk0 - tgtA) + ma0);
                float p1 = ex2(sc[nf][1] - BSC * fabsf(jk0 + 1.0f - tgtA) + ma1);
                float p2 = ex2(sc[nf][2] - BSC * fabsf(jk0 - tgtB) + ma0);
                float p3 = ex2(sc[nf][3] - BSC * fabsf(jk0 + 1.0f - tgtB) + ma1);
                s0 += p0 + p1;
                s1 += p2 + p3;
                uint32_t pb = (uint32_t)(PB - sb) + (uint32_t)r * 128
                            + ((uint32_t)(nf ^ (r & 7)) << 4) + 4 * t4;
                *(__half2*)(smc + pb)        = __floats2half2_rn(p0, p1);
                *(__half2*)(smc + pb + 1024) = __floats2half2_rn(p2, p3);
            }
            lp[mf][0] += s0;
            lp[mf][1] += s1;
        }
        __syncwarp();   // P stores visible to ldmatrix cross-lane

        // O += P @ V  (V^T in smem: rows d, cols s -> same B frag as K)
#pragma unroll
        for (int ks = 0; ks < 4; ks++) {
            const uint32_t cwA = (uint32_t)(((2 * ks + (tq >> 1)) ^ i7) << 4);
            const uint32_t cwB = (uint32_t)(((2 * ks + (tq & 1)) ^ i7) << 4);
            uint32_t p0v[4], p1v[4];
            LDSM4(p0v, PB + laneA + cwA);
            LDSM4(p1v, PB + laneA + 2048 + cwA);
            uint32_t bv[16];
#pragma unroll
            for (int np = 0; np < 4; np++)
                LDSM4(&bv[np * 4], VBc + laneB + np * 2048 + cwB);
#pragma unroll
            for (int nf = 0; nf < 8; nf++) {
                uint32_t b0 = bv[(nf >> 1) * 4 + (nf & 1) * 2];
                uint32_t b1 = bv[(nf >> 1) * 4 + (nf & 1) * 2 + 1];
                mma8(o[0][nf], p0v, b0, b1);
                mma8(o[1][nf], p1v, b0, b1);
            }
        }
        __syncwarp();
    }

    // ---- final row-sum reduction, normalize, write fp16 ----
#pragma unroll
    for (int mf = 0; mf < 2; mf++) {
        float l0 = lp[mf][0];
        float l1 = lp[mf][1];
        l0 += __shfl_xor_sync(0xffffffffu, l0, 1);
        l0 += __shfl_xor_sync(0xffffffffu, l0, 2);
        l1 += __shfl_xor_sync(0xffffffffu, l1, 1);
        l1 += __shfl_xor_sync(0xffffffffu, l1, 2);
        float inv0 = 1.0f / l0;
        float inv1 = 1.0f / l1;
        size_t r0 = ((size_t)(b * S_LEN + q0 + m0 + mf * 16 + g)) * E_DIM + h * D_HEAD;
        size_t r1 = r0 + 8 * E_DIM;
#pragma unroll
        for (int nf = 0; nf < 8; nf++) {
            int col = nf * 8 + 2 * t4;
            *(__half2*)&out[r0 + col] =
                __floats2half2_rn(o[mf][nf][0] * inv0, o[mf][nf][1] * inv0);
            *(__half2*)&out[r1 + col] =
                __floats2half2_rn(o[mf][nf][2] * inv1, o[mf][nf][3] * inv1);
        }
    }
}

// ---------------------------------------------------------------------------
extern "C" void kernel_launch(void* const* d_in, const int* in_sizes, int n_in,
                              void* d_out, int out_size)
{
    const float* x    = (const float*)d_in[0];
    const float* Wq   = (const float*)d_in[1];
    const float* Wk   = (const float*)d_in[2];
    const float* Wv   = (const float*)d_in[3];
    const float* Wo   = (const float*)d_in[4];
    const unsigned int* mask = (const unsigned int*)d_in[5];
    float* out = (float*)d_out;

    __half *xp, *wqp, *wkp, *wvp, *wop, *qp, *kp, *vp, *ap;
    cudaGetSymbolAddress((void**)&xp,  g_X);
    cudaGetSymbolAddress((void**)&wqp, g_Wq);
    cudaGetSymbolAddress((void**)&wkp, g_Wk);
    cudaGetSymbolAddress((void**)&wvp, g_Wv);
    cudaGetSymbolAddress((void**)&wop, g_Wo);
    cudaGetSymbolAddress((void**)&qp,  g_Q);
    cudaGetSymbolAddress((void**)&kp,  g_K);
    cudaGetSymbolAddress((void**)&vp,  g_V);
    cudaGetSymbolAddress((void**)&ap,  g_A);

    cudaFuncSetAttribute(gemm_tc, cudaFuncAttributeMaxDynamicSharedMemorySize, GEMM_SMEM);
    cudaFuncSetAttribute(attn_tc, cudaFuncAttributeMaxDynamicSharedMemorySize, ATT_SMEM);

    // 1. pre-convert inputs to fp16 (Wq scaled by 0.125*log2e)
    cvt_kernel<<<dim3(512, 1, 5), 256>>>((const float4*)x, (const float4*)Wq,
                                         (const float4*)Wk, (const float4*)Wv,
                                         (const float4*)Wo);

    // 2. fused QKV projections (V written transposed)
    gemm_tc<<<dim3(GN / 128, GM / 128, 3), 128, GEMM_SMEM>>>(
        xp, wqp, wkp, wvp, qp, kp, vp, 1);

    // 3. attention (128 threads / 4 warps, fp16, single barrier per tile)
    attn_tc<<<dim3(S_LEN / 128, H_NUM, B_SZ), 128, ATT_SMEM>>>(mask, ap);

    // 4. output projection (fp32 out)
    gemm_tc<<<dim3(GN / 128, GM / 128, 1), 128, GEMM_SMEM>>>(
        ap, wop, wop, wop, out, out, out, 0);
}

// round 11
// speedup vs baseline: 1.8609x; 1.0705x over previous
#include <cuda_runtime.h>
#include <cuda_fp16.h>
#include <cstdint>
#include <math.h>

// Problem constants
#define B_SZ   2
#define S_LEN  2048
#define E_DIM  1024
#define H_NUM  16
#define D_HEAD 64
#define ALPHA  0.5f
#define LOG2E  1.4426950408889634f

#define GM 4096
#define GN 1024
#define GK 1024

// Scratch (device globals — allocation-free), all fp16
__device__ __half g_X [GM * GK];
__device__ __half g_Wq[GN * GK];         // Wq * 0.125*log2e
__device__ __half g_Wk[GN * GK];
__device__ __half g_Wv[GN * GK];
__device__ __half g_Wo[GN * GK];
__device__ __half g_Q [GM * GN];         // pre-scaled, [b*S+s][h*64+d]
__device__ __half g_K [GM * GN];         // [b*S+s][h*64+d]
__device__ __half g_V [GM * GN];         // TRANSPOSED: [(b*1024 + h*64+d)][s]
__device__ __half g_A [GM * GN];

// ---------------------------------------------------------------------------
// Helpers
// ---------------------------------------------------------------------------
static __device__ __forceinline__ uint32_t smem_u32(const void* p) {
    uint32_t a;
    asm("{ .reg .u64 t; cvta.to.shared.u64 t, %1; cvt.u32.u64 %0, t; }" : "=r"(a) : "l"(p));
    return a;
}
static __device__ __forceinline__ float ex2(float x) {
    float y;
    asm("ex2.approx.f32 %0, %1;" : "=f"(y) : "f"(x));
    return y;
}
static __device__ __forceinline__ uint32_t packh2(float a, float b) {
    __half2 h = __floats2half2_rn(a, b);
    return *(uint32_t*)&h;
}
static __device__ __forceinline__ void cp16(uint32_t dst, const void* src) {
    asm volatile("cp.async.cg.shared.global [%0], [%1], 16;" :: "r"(dst), "l"(src));
}
static __device__ __forceinline__ void cp_commit() {
    asm volatile("cp.async.commit_group;" ::: "memory");
}
static __device__ __forceinline__ void cp_wait0() {
    asm volatile("cp.async.wait_group 0;" ::: "memory");
}
static __device__ __forceinline__ void cp_wait1() {
    asm volatile("cp.async.wait_group 1;" ::: "memory");
}
#define LDSM4(R, ADDR)                                                        \
    asm volatile("ldmatrix.sync.aligned.m8n8.x4.shared.b16 {%0,%1,%2,%3}, [%4];" \
        : "=r"((R)[0]), "=r"((R)[1]), "=r"((R)[2]), "=r"((R)[3]) : "r"(ADDR))

// D += A(16x16) @ B(16x8), fp16 inputs, f32 accumulate
static __device__ __forceinline__ void mma8(float* d, const uint32_t* a,
                                            uint32_t b0, uint32_t b1) {
    asm volatile(
        "mma.sync.aligned.m16n8k16.row.col.f32.f16.f16.f32 "
        "{%0,%1,%2,%3}, {%4,%5,%6,%7}, {%8,%9}, {%0,%1,%2,%3};"
        : "+f"(d[0]), "+f"(d[1]), "+f"(d[2]), "+f"(d[3])
        : "r"(a[0]), "r"(a[1]), "r"(a[2]), "r"(a[3]), "r"(b0), "r"(b1));
}

// ---------------------------------------------------------------------------
// Pre-convert inputs to FP16 (scale folded for Wq)
// ---------------------------------------------------------------------------
__global__ __launch_bounds__(256)
void cvt_kernel(const float4* __restrict__ x,  const float4* __restrict__ wq,
                const float4* __restrict__ wk, const float4* __restrict__ wv,
                const float4* __restrict__ wo)
{
    const int z = blockIdx.z;
    const float4* src;
    __half2* dst;
    int n4;
    float s = 1.0f;
    switch (z) {
        case 0: src = x;  dst = (__half2*)g_X;  n4 = GM * GK / 4; break;
        case 1: src = wq; dst = (__half2*)g_Wq; n4 = GN * GK / 4; s = 0.125f * LOG2E; break;
        case 2: src = wk; dst = (__half2*)g_Wk; n4 = GN * GK / 4; break;
        case 3: src = wv; dst = (__half2*)g_Wv; n4 = GN * GK / 4; break;
        default: src = wo; dst = (__half2*)g_Wo; n4 = GN * GK / 4; break;
    }
    for (int i = blockIdx.x * 256 + threadIdx.x; i < n4; i += gridDim.x * 256) {
        float4 v = src[i];
        dst[2 * i]     = __floats2half2_rn(v.x * s, v.y * s);
        dst[2 * i + 1] = __floats2half2_rn(v.z * s, v.w * s);
    }
}

// ---------------------------------------------------------------------------
// FP16 GEMM (unchanged): C = A[M,K] @ W[N,K]^T, f32 accum.
// ---------------------------------------------------------------------------
#define GEMM_SMEM (3 * 32768)

__global__ __launch_bounds__(128, 2)
void gemm_tc(const __half* __restrict__ A,
             const __half* __restrict__ W0, const __half* __restrict__ W1,
             const __half* __restrict__ W2,
             void* __restrict__ C0, void* __restrict__ C1, void* __restrict__ C2,
             int cvt_out)
{
    extern __shared__ char smc[];
    const uint32_t sb = smem_u32(smc);

    const __half* W = (blockIdx.z == 0) ? W0 : (blockIdx.z == 1) ? W1 : W2;
    void*         C = (blockIdx.z == 0) ? C0 : (blockIdx.z == 1) ? C1 : C2;

    const int t    = threadIdx.x;
    const int w    = t >> 5;
    const int lane = t & 31;
    const int g    = lane >> 2;
    const int t4   = lane & 3;
    const int i7   = lane & 7;
    const int tq   = lane >> 3;
    const int m0   = (w >> 1) * 64;
    const int n0   = (w & 1) * 64;
    const int bm   = blockIdx.y * 128;
    const int bn   = blockIdx.x * 128;

    const uint32_t laneA = (uint32_t)(m0 + ((tq & 1) << 3) + i7) * 128;
    const uint32_t laneB = (uint32_t)(n0 + ((tq & 2) << 2) + i7) * 128;

    float acc[4][8][4];
#pragma unroll
    for (int mf = 0; mf < 4; mf++)
#pragma unroll
        for (int nf = 0; nf < 8; nf++)
#pragma unroll
            for (int r = 0; r < 4; r++) acc[mf][nf][r] = 0.0f;

#define GEMM_ISSUE(CH) do {                                                     \
        const int _k0 = (CH) * 64;                                              \
        const uint32_t _sa = sb + ((CH) % 3) * 32768;                           \
        _Pragma("unroll")                                                       \
        for (int _i = 0; _i < 8; _i++) {                                        \
            int _idx = _i * 128 + t;                                            \
            int _row = _idx >> 3;                                               \
            int _wd  = _idx & 7;                                                \
            uint32_t _o = (uint32_t)(_row * 128 + (((_wd) ^ (_row & 7)) << 4)); \
            cp16(_sa + _o,         &A[(size_t)(bm + _row) * GK + _k0 + _wd * 8]); \
            cp16(_sa + 16384 + _o, &W[(size_t)(bn + _row) * GK + _k0 + _wd * 8]); \
        }                                                                       \
        cp_commit();                                                            \
    } while (0)

    GEMM_ISSUE(0);
    GEMM_ISSUE(1);

    for (int ch = 0; ch < 16; ch++) {
        if (ch < 15) cp_wait1(); else cp_wait0();
        __syncthreads();
        if (ch + 2 < 16) GEMM_ISSUE(ch + 2);

        const uint32_t stage = sb + (ch % 3) * 32768;
#pragma unroll
        for (int ks = 0; ks < 4; ks++) {
            const uint32_t cwA = (uint32_t)(((2 * ks + (tq >> 1)) ^ i7) << 4);
            const uint32_t cwB = (uint32_t)(((2 * ks + (tq & 1)) ^ i7) << 4);
            uint32_t av[4][4];
#pragma unroll
            for (int mf = 0; mf < 4; mf++)
                LDSM4(av[mf], stage + laneA + mf * 2048 + cwA);
            uint32_t bv[16];
#pragma unroll
            for (int np = 0; np < 4; np++)
                LDSM4(&bv[np * 4], stage + 16384 + laneB + np * 2048 + cwB);
#pragma unroll
            for (int nf = 0; nf < 8; nf++) {
                uint32_t b0 = bv[(nf >> 1) * 4 + (nf & 1) * 2];
                uint32_t b1 = bv[(nf >> 1) * 4 + (nf & 1) * 2 + 1];
#pragma unroll
                for (int mf = 0; mf < 4; mf++)
                    mma8(acc[mf][nf], av[mf], b0, b1);
            }
        }
    }

    // epilogue
    if (cvt_out && blockIdx.z == 2) {
        __half* Ch = (__half*)C;
        const int bb = bm >> 11;
#pragma unroll
        for (int mf = 0; mf < 4; mf++) {
            int row = bm + m0 + mf * 16 + g;
            int s   = row & (S_LEN - 1);
#pragma unroll
            for (int nf = 0; nf < 8; nf++) {
                int col = bn + n0 + nf * 8 + 2 * t4;
                size_t base = ((size_t)(bb * 1024 + col)) * S_LEN + s;
                Ch[base]             = __float2half_rn(acc[mf][nf][0]);
                Ch[base + S_LEN]     = __float2half_rn(acc[mf][nf][1]);
                Ch[base + 8]         = __float2half_rn(acc[mf][nf][2]);
                Ch[base + S_LEN + 8] = __float2half_rn(acc[mf][nf][3]);
            }
        }
    } else if (cvt_out) {
        __half* Ch = (__half*)C;
#pragma unroll
        for (int mf = 0; mf < 4; mf++) {
            int row = bm + m0 + mf * 16 + g;
#pragma unroll
            for (int nf = 0; nf < 8; nf++) {
                int col = bn + n0 + nf * 8 + 2 * t4;
                *(__half2*)&Ch[(size_t)row * GN + col] =
                    __floats2half2_rn(acc[mf][nf][0], acc[mf][nf][1]);
                *(__half2*)&Ch[(size_t)(row + 8) * GN + col] =
                    __floats2half2_rn(acc[mf][nf][2], acc[mf][nf][3]);
            }
        }
    } else {
        float* Cf = (float*)C;
#pragma unroll
        for (int mf = 0; mf < 4; mf++) {
            int row = bm + m0 + mf * 16 + g;
#pragma unroll
            for (int nf = 0; nf < 8; nf++) {
                int col = bn + n0 + nf * 8 + 2 * t4;
                *(float2*)&Cf[(size_t)row * GN + col] =
                    make_float2(acc[mf][nf][0], acc[mf][nf][1]);
                *(float2*)&Cf[(size_t)(row + 8) * GN + col] =
                    make_float2(acc[mf][nf][2], acc[mf][nf][3]);
            }
        }
    }
#undef GEMM_ISSUE
}

// ---------------------------------------------------------------------------
// FP16 flash attention: no-max exp2 softmax, ONE barrier per tile,
// REGISTER-RESIDENT P (QK C-frags pack directly into PV A-frags — no smem
// round trip, no syncwarp).  K and V double-buffered, prefetched one tile
// ahead together with the mask additive.
// SMEM: Q @0 (16K), K0 @16384, K1 @24576, V0 @32768, V1 @40960 (8K each),
//       madd @49152 (512B).  Total 49,664 B -> 3 CTAs/SM.
// ---------------------------------------------------------------------------
#define ATT_SMEM 49664

__global__ __launch_bounds__(128, 3)
void attn_tc(const unsigned int* __restrict__ mask, __half* __restrict__ out)
{
    extern __shared__ char smc[];
    const uint32_t sb  = smem_u32(smc);
    const uint32_t QB  = sb;
    const uint32_t KB0 = sb + 16384;
    const uint32_t VB0 = sb + 32768;
    float* maddf = (float*)(smc + 49152);

    const int t    = threadIdx.x;
    const int w    = t >> 5;
    const int lane = t & 31;
    const int g    = lane >> 2;
    const int t4   = lane & 3;
    const int i7   = lane & 7;
    const int tq   = lane >> 3;
    const int q0   = blockIdx.x * 128;
    const int h    = blockIdx.y;
    const int b    = blockIdx.z;
    const int m0   = w * 32;

    const float BSC = ALPHA * LOG2E / (float)S_LEN;

    // ldmatrix per-lane row bases (bytes; 128B rows)
    const uint32_t laneA = (uint32_t)(m0 + ((tq & 1) << 3) + i7) * 128;   // Q
    const uint32_t laneB = (uint32_t)(((tq & 2) << 2) + i7) * 128;        // K, V^T

    // prologue: Q + K(0) + V(0) in one group; madd[0]
#pragma unroll
    for (int i = 0; i < 8; i++) {
        int idx = i * 128 + t;
        int row = idx >> 3;
        int wd  = idx & 7;
        cp16(QB + (uint32_t)(row * 128 + ((wd ^ (row & 7)) << 4)),
             &g_Q[((size_t)(b * S_LEN + q0 + row)) * E_DIM + h * D_HEAD + wd * 8]);
    }
#pragma unroll
    for (int i = 0; i < 4; i++) {
        int idx = i * 128 + t;
        int row = idx >> 3;
        int wd  = idx & 7;
        uint32_t so = (uint32_t)(row * 128 + ((wd ^ (row & 7)) << 4));
        cp16(KB0 + so, &g_K[((size_t)(b * S_LEN + row)) * E_DIM + h * D_HEAD + wd * 8]);
        cp16(VB0 + so, &g_V[((size_t)(b * 1024 + h * D_HEAD + row)) * S_LEN + wd * 8]);
    }
    cp_commit();
    if (t < 64)
        maddf[t] = (mask[b * S_LEN + t] != 0u) ? -1e30f : 0.0f;

    float o[2][8][4];
#pragma unroll
    for (int mf = 0; mf < 2; mf++)
#pragma unroll
        for (int nf = 0; nf < 8; nf++)
#pragma unroll
            for (int r = 0; r < 4; r++) o[mf][nf][r] = 0.0f;

    float lp[2][2] = {{0.0f, 0.0f}, {0.0f, 0.0f}};
    const float tgt00 = (float)(S_LEN - 1 - (q0 + m0 + g));

    for (int kt = 0; kt < 32; kt++) {
        const int k0g = kt * 64;
        const uint32_t KB  = KB0 + ((uint32_t)(kt & 1) << 13);
        const uint32_t VBc = VB0 + ((uint32_t)(kt & 1) << 13);

        // single sync point: K(kt), V(kt) complete + visible; alt buffers free
        cp_wait0();
        __syncthreads();

        // issue K(kt+1), V(kt+1), mask(kt+1)
        if (kt < 31) {
            const uint32_t KBn = KB0 + ((uint32_t)(~kt & 1) << 13);
            const uint32_t VBn = VB0 + ((uint32_t)(~kt & 1) << 13);
#pragma unroll
            for (int i = 0; i < 4; i++) {
                int idx = i * 128 + t;
                int row = idx >> 3;
                int wd  = idx & 7;
                uint32_t so = (uint32_t)(row * 128 + ((wd ^ (row & 7)) << 4));
                cp16(KBn + so,
                     &g_K[((size_t)(b * S_LEN + k0g + 64 + row)) * E_DIM + h * D_HEAD + wd * 8]);
                cp16(VBn + so,
                     &g_V[((size_t)(b * 1024 + h * D_HEAD + row)) * S_LEN + k0g + 64 + wd * 8]);
            }
            cp_commit();
            if (t < 64)
                maddf[(~kt & 1) * 64 + t] =
                    (mask[b * S_LEN + k0g + 64 + t] != 0u) ? -1e30f : 0.0f;
        }

        const float* md = maddf + (kt & 1) * 64;

        // per mf: QK -> softmax (register P) -> PV
#pragma unroll
        for (int mf = 0; mf < 2; mf++) {
            float sc[8][4];
#pragma unroll
            for (int nf = 0; nf < 8; nf++)
#pragma unroll
                for (int r = 0; r < 4; r++) sc[nf][r] = 0.0f;

#pragma unroll
            for (int ks = 0; ks < 4; ks++) {
                const uint32_t cwA = (uint32_t)(((2 * ks + (tq >> 1)) ^ i7) << 4);
                const uint32_t cwB = (uint32_t)(((2 * ks + (tq & 1)) ^ i7) << 4);
                uint32_t av[4];
                LDSM4(av, QB + laneA + mf * 2048 + cwA);
                uint32_t bv[16];
#pragma unroll
                for (int np = 0; np < 4; np++)
                    LDSM4(&bv[np * 4], KB + laneB + np * 2048 + cwB);
#pragma unroll
                for (int nf = 0; nf < 8; nf++) {
                    uint32_t b0 = bv[(nf >> 1) * 4 + (nf & 1) * 2];
                    uint32_t b1 = bv[(nf >> 1) * 4 + (nf & 1) * 2 + 1];
                    mma8(sc[nf], av, b0, b1);
                }
            }

            // bias + mask + p = ex2(s); pack P into PV A-fragments (registers)
            const float tgtA = tgt00 - (float)(mf * 16);
            const float tgtB = tgtA - 8.0f;
            uint32_t pa[16];
            float s0 = 0.0f, s1 = 0.0f;
#pragma unroll
            for (int nf = 0; nf < 8; nf++) {
                int jc = nf * 8 + 2 * t4;
                float jk0 = (float)(k0g + jc);
                float2 ma = *(const float2*)&md[jc];
                float p0 = ex2(sc[nf][0] - BSC * fabsf(jk0 - tgtA) + ma.x);
                float p1 = ex2(sc[nf][1] - BSC * fabsf(jk0 + 1.0f - tgtA) + ma.y);
                float p2 = ex2(sc[nf][2] - BSC * fabsf(jk0 - tgtB) + ma.x);
                float p3 = ex2(sc[nf][3] - BSC * fabsf(jk0 + 1.0f - tgtB) + ma.y);
                s0 += p0 + p1;
                s1 += p2 + p3;
                pa[2 * nf]     = packh2(p0, p1);   // rows g,   keys jc..jc+1
                pa[2 * nf + 1] = packh2(p2, p3);   // rows g+8
            }
            lp[mf][0] += s0;
            lp[mf][1] += s1;

            // O[mf] += P @ V  (A from registers; V^T B-frags from smem)
#pragma unroll
            for (int ks = 0; ks < 4; ks++) {
                const uint32_t cwB = (uint32_t)(((2 * ks + (tq & 1)) ^ i7) << 4);
                uint32_t bv[16];
#pragma unroll
                for (int np = 0; np < 4; np++)
                    LDSM4(&bv[np * 4], VBc + laneB + np * 2048 + cwB);
#pragma unroll
                for (int nf = 0; nf < 8; nf++) {
                    uint32_t b0 = bv[(nf >> 1) * 4 + (nf & 1) * 2];
                    uint32_t b1 = bv[(nf >> 1) * 4 + (nf & 1) * 2 + 1];
                    mma8(o[mf][nf], &pa[4 * ks], b0, b1);
                }
            }
        }
    }

    // ---- final row-sum reduction, normalize, write fp16 ----
#pragma unroll
    for (int mf = 0; mf < 2; mf++) {
        float l0 = lp[mf][0];
        float l1 = lp[mf][1];
        l0 += __shfl_xor_sync(0xffffffffu, l0, 1);
        l0 += __shfl_xor_sync(0xffffffffu, l0, 2);
        l1 += __shfl_xor_sync(0xffffffffu, l1, 1);
        l1 += __shfl_xor_sync(0xffffffffu, l1, 2);
        float inv0 = 1.0f / l0;
        float inv1 = 1.0f / l1;
        size_t r0 = ((size_t)(b * S_LEN + q0 + m0 + mf * 16 + g)) * E_DIM + h * D_HEAD;
        size_t r1 = r0 + 8 * E_DIM;
#pragma unroll
        for (int nf = 0; nf < 8; nf++) {
            int col = nf * 8 + 2 * t4;
            *(__half2*)&out[r0 + col] =
                __floats2half2_rn(o[mf][nf][0] * inv0, o[mf][nf][1] * inv0);
            *(__half2*)&out[r1 + col] =
                __floats2half2_rn(o[mf][nf][2] * inv1, o[mf][nf][3] * inv1);
        }
    }
}

// ---------------------------------------------------------------------------
extern "C" void kernel_launch(void* const* d_in, const int* in_sizes, int n_in,
                              void* d_out, int out_size)
{
    const float* x    = (const float*)d_in[0];
    const float* Wq   = (const float*)d_in[1];
    const float* Wk   = (const float*)d_in[2];
    const float* Wv   = (const float*)d_in[3];
    const float* Wo   = (const float*)d_in[4];
    const unsigned int* mask = (const unsigned int*)d_in[5];
    float* out = (float*)d_out;

    __half *xp, *wqp, *wkp, *wvp, *wop, *qp, *kp, *vp, *ap;
    cudaGetSymbolAddress((void**)&xp,  g_X);
    cudaGetSymbolAddress((void**)&wqp, g_Wq);
    cudaGetSymbolAddress((void**)&wkp, g_Wk);
    cudaGetSymbolAddress((void**)&wvp, g_Wv);
    cudaGetSymbolAddress((void**)&wop, g_Wo);
    cudaGetSymbolAddress((void**)&qp,  g_Q);
    cudaGetSymbolAddress((void**)&kp,  g_K);
    cudaGetSymbolAddress((void**)&vp,  g_V);
    cudaGetSymbolAddress((void**)&ap,  g_A);

    cudaFuncSetAttribute(gemm_tc, cudaFuncAttributeMaxDynamicSharedMemorySize, GEMM_SMEM);
    cudaFuncSetAttribute(attn_tc, cudaFuncAttributeMaxDynamicSharedMemorySize, ATT_SMEM);

    // 1. pre-convert inputs to fp16 (Wq scaled by 0.125*log2e)
    cvt_kernel<<<dim3(512, 1, 5), 256>>>((const float4*)x, (const float4*)Wq,
                                         (const float4*)Wk, (const float4*)Wv,
                                         (const float4*)Wo);

    // 2. fused QKV projections (V written transposed)
    gemm_tc<<<dim3(GN / 128, GM / 128, 3), 128, GEMM_SMEM>>>(
        xp, wqp, wkp, wvp, qp, kp, vp, 1);

    // 3. attention (register-resident P)
    attn_tc<<<dim3(S_LEN / 128, H_NUM, B_SZ), 128, ATT_SMEM>>>(mask, ap);

    // 4. output projection (fp32 out)
    gemm_tc<<<dim3(GN / 128, GM / 128, 1), 128, GEMM_SMEM>>>(
        ap, wop, wop, wop, out, out, out, 0);
}

// round 12
// speedup vs baseline: 2.0103x; 1.0803x over previous
#include <cuda_runtime.h>
#include <cuda_fp16.h>
#include <cstdint>
#include <math.h>

// Problem constants
#define B_SZ   2
#define S_LEN  2048
#define E_DIM  1024
#define H_NUM  16
#define D_HEAD 64
#define ALPHA  0.5f
#define LOG2E  1.4426950408889634f

#define GM 4096
#define GN 1024
#define GK 1024

// Scratch (device globals — allocation-free), all fp16
__device__ __half g_X [GM * GK];
__device__ __half g_Wq[GN * GK];         // Wq * 0.125*log2e
__device__ __half g_Wk[GN * GK];
__device__ __half g_Wv[GN * GK];
__device__ __half g_Wo[GN * GK];
__device__ __half g_Q [GM * GN];         // pre-scaled, [b*S+s][h*64+d]
__device__ __half g_K [GM * GN];         // [b*S+s][h*64+d]
__device__ __half g_V [GM * GN];         // TRANSPOSED: [(b*1024 + h*64+d)][s]
__device__ __half g_A [GM * GN];

// ---------------------------------------------------------------------------
// Helpers
// ---------------------------------------------------------------------------
static __device__ __forceinline__ uint32_t smem_u32(const void* p) {
    uint32_t a;
    asm("{ .reg .u64 t; cvta.to.shared.u64 t, %1; cvt.u32.u64 %0, t; }" : "=r"(a) : "l"(p));
    return a;
}
static __device__ __forceinline__ float ex2(float x) {
    float y;
    asm("ex2.approx.f32 %0, %1;" : "=f"(y) : "f"(x));
    return y;
}
static __device__ __forceinline__ uint32_t packh2(float a, float b) {
    __half2 h = __floats2half2_rn(a, b);
    return *(uint32_t*)&h;
}
static __device__ __forceinline__ void cp16(uint32_t dst, const void* src) {
    asm volatile("cp.async.cg.shared.global [%0], [%1], 16;" :: "r"(dst), "l"(src));
}
static __device__ __forceinline__ void cp_commit() {
    asm volatile("cp.async.commit_group;" ::: "memory");
}
static __device__ __forceinline__ void cp_wait0() {
    asm volatile("cp.async.wait_group 0;" ::: "memory");
}
static __device__ __forceinline__ void cp_wait1() {
    asm volatile("cp.async.wait_group 1;" ::: "memory");
}
#define LDSM4(R, ADDR)                                                        \
    asm volatile("ldmatrix.sync.aligned.m8n8.x4.shared.b16 {%0,%1,%2,%3}, [%4];" \
        : "=r"((R)[0]), "=r"((R)[1]), "=r"((R)[2]), "=r"((R)[3]) : "r"(ADDR))

// D += A(16x16) @ B(16x8), fp16 inputs, f32 accumulate
static __device__ __forceinline__ void mma8(float* d, const uint32_t* a,
                                            uint32_t b0, uint32_t b1) {
    asm volatile(
        "mma.sync.aligned.m16n8k16.row.col.f32.f16.f16.f32 "
        "{%0,%1,%2,%3}, {%4,%5,%6,%7}, {%8,%9}, {%0,%1,%2,%3};"
        : "+f"(d[0]), "+f"(d[1]), "+f"(d[2]), "+f"(d[3])
        : "r"(a[0]), "r"(a[1]), "r"(a[2]), "r"(a[3]), "r"(b0), "r"(b1));
}

// ---------------------------------------------------------------------------
// Pre-convert inputs to FP16 (scale folded for Wq)
// ---------------------------------------------------------------------------
__global__ __launch_bounds__(256)
void cvt_kernel(const float4* __restrict__ x,  const float4* __restrict__ wq,
                const float4* __restrict__ wk, const float4* __restrict__ wv,
                const float4* __restrict__ wo)
{
    const int z = blockIdx.z;
    const float4* src;
    __half2* dst;
    int n4;
    float s = 1.0f;
    switch (z) {
        case 0: src = x;  dst = (__half2*)g_X;  n4 = GM * GK / 4; break;
        case 1: src = wq; dst = (__half2*)g_Wq; n4 = GN * GK / 4; s = 0.125f * LOG2E; break;
        case 2: src = wk; dst = (__half2*)g_Wk; n4 = GN * GK / 4; break;
        case 3: src = wv; dst = (__half2*)g_Wv; n4 = GN * GK / 4; break;
        default: src = wo; dst = (__half2*)g_Wo; n4 = GN * GK / 4; break;
    }
    for (int i = blockIdx.x * 256 + threadIdx.x; i < n4; i += gridDim.x * 256) {
        float4 v = src[i];
        dst[2 * i]     = __floats2half2_rn(v.x * s, v.y * s);
        dst[2 * i + 1] = __floats2half2_rn(v.z * s, v.w * s);
    }
}

// ---------------------------------------------------------------------------
// FP16 GEMM (unchanged): C = A[M,K] @ W[N,K]^T, f32 accum.
// ---------------------------------------------------------------------------
#define GEMM_SMEM (3 * 32768)

__global__ __launch_bounds__(128, 2)
void gemm_tc(const __half* __restrict__ A,
             const __half* __restrict__ W0, const __half* __restrict__ W1,
             const __half* __restrict__ W2,
             void* __restrict__ C0, void* __restrict__ C1, void* __restrict__ C2,
             int cvt_out)
{
    extern __shared__ char smc[];
    const uint32_t sb = smem_u32(smc);

    const __half* W = (blockIdx.z == 0) ? W0 : (blockIdx.z == 1) ? W1 : W2;
    void*         C = (blockIdx.z == 0) ? C0 : (blockIdx.z == 1) ? C1 : C2;

    const int t    = threadIdx.x;
    const int w    = t >> 5;
    const int lane = t & 31;
    const int g    = lane >> 2;
    const int t4   = lane & 3;
    const int i7   = lane & 7;
    const int tq   = lane >> 3;
    const int m0   = (w >> 1) * 64;
    const int n0   = (w & 1) * 64;
    const int bm   = blockIdx.y * 128;
    const int bn   = blockIdx.x * 128;

    const uint32_t laneA = (uint32_t)(m0 + ((tq & 1) << 3) + i7) * 128;
    const uint32_t laneB = (uint32_t)(n0 + ((tq & 2) << 2) + i7) * 128;

    float acc[4][8][4];
#pragma unroll
    for (int mf = 0; mf < 4; mf++)
#pragma unroll
        for (int nf = 0; nf < 8; nf++)
#pragma unroll
            for (int r = 0; r < 4; r++) acc[mf][nf][r] = 0.0f;

#define GEMM_ISSUE(CH) do {                                                     \
        const int _k0 = (CH) * 64;                                              \
        const uint32_t _sa = sb + ((CH) % 3) * 32768;                           \
        _Pragma("unroll")                                                       \
        for (int _i = 0; _i < 8; _i++) {                                        \
            int _idx = _i * 128 + t;                                            \
            int _row = _idx >> 3;                                               \
            int _wd  = _idx & 7;                                                \
            uint32_t _o = (uint32_t)(_row * 128 + (((_wd) ^ (_row & 7)) << 4)); \
            cp16(_sa + _o,         &A[(size_t)(bm + _row) * GK + _k0 + _wd * 8]); \
            cp16(_sa + 16384 + _o, &W[(size_t)(bn + _row) * GK + _k0 + _wd * 8]); \
        }                                                                       \
        cp_commit();                                                            \
    } while (0)

    GEMM_ISSUE(0);
    GEMM_ISSUE(1);

    for (int ch = 0; ch < 16; ch++) {
        if (ch < 15) cp_wait1(); else cp_wait0();
        __syncthreads();
        if (ch + 2 < 16) GEMM_ISSUE(ch + 2);

        const uint32_t stage = sb + (ch % 3) * 32768;
#pragma unroll
        for (int ks = 0; ks < 4; ks++) {
            const uint32_t cwA = (uint32_t)(((2 * ks + (tq >> 1)) ^ i7) << 4);
            const uint32_t cwB = (uint32_t)(((2 * ks + (tq & 1)) ^ i7) << 4);
            uint32_t av[4][4];
#pragma unroll
            for (int mf = 0; mf < 4; mf++)
                LDSM4(av[mf], stage + laneA + mf * 2048 + cwA);
            uint32_t bv[16];
#pragma unroll
            for (int np = 0; np < 4; np++)
                LDSM4(&bv[np * 4], stage + 16384 + laneB + np * 2048 + cwB);
#pragma unroll
            for (int nf = 0; nf < 8; nf++) {
                uint32_t b0 = bv[(nf >> 1) * 4 + (nf & 1) * 2];
                uint32_t b1 = bv[(nf >> 1) * 4 + (nf & 1) * 2 + 1];
#pragma unroll
                for (int mf = 0; mf < 4; mf++)
                    mma8(acc[mf][nf], av[mf], b0, b1);
            }
        }
    }

    // epilogue
    if (cvt_out && blockIdx.z == 2) {
        __half* Ch = (__half*)C;
        const int bb = bm >> 11;
#pragma unroll
        for (int mf = 0; mf < 4; mf++) {
            int row = bm + m0 + mf * 16 + g;
            int s   = row & (S_LEN - 1);
#pragma unroll
            for (int nf = 0; nf < 8; nf++) {
                int col = bn + n0 + nf * 8 + 2 * t4;
                size_t base = ((size_t)(bb * 1024 + col)) * S_LEN + s;
                Ch[base]             = __float2half_rn(acc[mf][nf][0]);
                Ch[base + S_LEN]     = __float2half_rn(acc[mf][nf][1]);
                Ch[base + 8]         = __float2half_rn(acc[mf][nf][2]);
                Ch[base + S_LEN + 8] = __float2half_rn(acc[mf][nf][3]);
            }
        }
    } else if (cvt_out) {
        __half* Ch = (__half*)C;
#pragma unroll
        for (int mf = 0; mf < 4; mf++) {
            int row = bm + m0 + mf * 16 + g;
#pragma unroll
            for (int nf = 0; nf < 8; nf++) {
                int col = bn + n0 + nf * 8 + 2 * t4;
                *(__half2*)&Ch[(size_t)row * GN + col] =
                    __floats2half2_rn(acc[mf][nf][0], acc[mf][nf][1]);
                *(__half2*)&Ch[(size_t)(row + 8) * GN + col] =
                    __floats2half2_rn(acc[mf][nf][2], acc[mf][nf][3]);
            }
        }
    } else {
        float* Cf = (float*)C;
#pragma unroll
        for (int mf = 0; mf < 4; mf++) {
            int row = bm + m0 + mf * 16 + g;
#pragma unroll
            for (int nf = 0; nf < 8; nf++) {
                int col = bn + n0 + nf * 8 + 2 * t4;
                *(float2*)&Cf[(size_t)row * GN + col] =
                    make_float2(acc[mf][nf][0], acc[mf][nf][1]);
                *(float2*)&Cf[(size_t)(row + 8) * GN + col] =
                    make_float2(acc[mf][nf][2], acc[mf][nf][3]);
            }
        }
    }
#undef GEMM_ISSUE
}

// ---------------------------------------------------------------------------
// FP16 flash attention: q-tile 64, 4 warps x 16 query rows (one mf each).
// Register-resident P, no-max exp2 softmax, K/V double-buffered with
// one-tile-ahead prefetch, single barrier per tile.
// SMEM: Q @0 (8K), K0 @8192, K1 @16384, V0 @24576, V1 @32768 (8K each),
//       madd @40960 (512B).  Total 41,472 B -> 3 CTAs/SM, regs ~130 (no spill).
// ---------------------------------------------------------------------------
#define ATT_SMEM 41472

__global__ __launch_bounds__(128, 3)
void attn_tc(const unsigned int* __restrict__ mask, __half* __restrict__ out)
{
    extern __shared__ char smc[];
    const uint32_t sb  = smem_u32(smc);
    const uint32_t QB  = sb;
    const uint32_t KB0 = sb + 8192;
    const uint32_t VB0 = sb + 24576;
    float* maddf = (float*)(smc + 40960);

    const int t    = threadIdx.x;
    const int w    = t >> 5;
    const int lane = t & 31;
    const int g    = lane >> 2;
    const int t4   = lane & 3;
    const int i7   = lane & 7;
    const int tq   = lane >> 3;
    const int q0   = blockIdx.x * 64;
    const int h    = blockIdx.y;
    const int b    = blockIdx.z;
    const int m0   = w * 16;               // 16 query rows per warp

    const float BSC = ALPHA * LOG2E / (float)S_LEN;

    // ldmatrix per-lane row bases (bytes; 128B rows)
    const uint32_t laneA = (uint32_t)(m0 + ((tq & 1) << 3) + i7) * 128;   // Q
    const uint32_t laneB = (uint32_t)(((tq & 2) << 2) + i7) * 128;        // K, V^T

    // prologue: Q (4 cp16/thr) + K(0) + V(0); madd[0]
#pragma unroll
    for (int i = 0; i < 4; i++) {
        int idx = i * 128 + t;
        int row = idx >> 3;
        int wd  = idx & 7;
        cp16(QB + (uint32_t)(row * 128 + ((wd ^ (row & 7)) << 4)),
             &g_Q[((size_t)(b * S_LEN + q0 + row)) * E_DIM + h * D_HEAD + wd * 8]);
    }
#pragma unroll
    for (int i = 0; i < 4; i++) {
        int idx = i * 128 + t;
        int row = idx >> 3;
        int wd  = idx & 7;
        uint32_t so = (uint32_t)(row * 128 + ((wd ^ (row & 7)) << 4));
        cp16(KB0 + so, &g_K[((size_t)(b * S_LEN + row)) * E_DIM + h * D_HEAD + wd * 8]);
        cp16(VB0 + so, &g_V[((size_t)(b * 1024 + h * D_HEAD + row)) * S_LEN + wd * 8]);
    }
    cp_commit();
    if (t < 64)
        maddf[t] = (mask[b * S_LEN + t] != 0u) ? -1e30f : 0.0f;

    float o[8][4];
#pragma unroll
    for (int nf = 0; nf < 8; nf++)
#pragma unroll
        for (int r = 0; r < 4; r++) o[nf][r] = 0.0f;

    float lp0 = 0.0f, lp1 = 0.0f;
    const float tgtA = (float)(S_LEN - 1 - (q0 + m0 + g));
    const float tgtB = tgtA - 8.0f;

    for (int kt = 0; kt < 32; kt++) {
        const int k0g = kt * 64;
        const uint32_t KB  = KB0 + ((uint32_t)(kt & 1) << 13);
        const uint32_t VBc = VB0 + ((uint32_t)(kt & 1) << 13);

        // single sync point: K(kt), V(kt) complete + visible; alt buffers free
        cp_wait0();
        __syncthreads();

        // issue K(kt+1), V(kt+1), mask(kt+1)
        if (kt < 31) {
            const uint32_t KBn = KB0 + ((uint32_t)(~kt & 1) << 13);
            const uint32_t VBn = VB0 + ((uint32_t)(~kt & 1) << 13);
#pragma unroll
            for (int i = 0; i < 4; i++) {
                int idx = i * 128 + t;
                int row = idx >> 3;
                int wd  = idx & 7;
                uint32_t so = (uint32_t)(row * 128 + ((wd ^ (row & 7)) << 4));
                cp16(KBn + so,
                     &g_K[((size_t)(b * S_LEN + k0g + 64 + row)) * E_DIM + h * D_HEAD + wd * 8]);
                cp16(VBn + so,
                     &g_V[((size_t)(b * 1024 + h * D_HEAD + row)) * S_LEN + k0g + 64 + wd * 8]);
            }
            cp_commit();
            if (t < 64)
                maddf[(~kt & 1) * 64 + t] =
                    (mask[b * S_LEN + k0g + 64 + t] != 0u) ? -1e30f : 0.0f;
        }

        const float* md = maddf + (kt & 1) * 64;

        // QK (this warp's 16 rows)
        float sc[8][4];
#pragma unroll
        for (int nf = 0; nf < 8; nf++)
#pragma unroll
            for (int r = 0; r < 4; r++) sc[nf][r] = 0.0f;

#pragma unroll
        for (int ks = 0; ks < 4; ks++) {
            const uint32_t cwA = (uint32_t)(((2 * ks + (tq >> 1)) ^ i7) << 4);
            const uint32_t cwB = (uint32_t)(((2 * ks + (tq & 1)) ^ i7) << 4);
            uint32_t av[4];
            LDSM4(av, QB + laneA + cwA);
            uint32_t bv[16];
#pragma unroll
            for (int np = 0; np < 4; np++)
                LDSM4(&bv[np * 4], KB + laneB + np * 2048 + cwB);
#pragma unroll
            for (int nf = 0; nf < 8; nf++) {
                uint32_t b0 = bv[(nf >> 1) * 4 + (nf & 1) * 2];
                uint32_t b1 = bv[(nf >> 1) * 4 + (nf & 1) * 2 + 1];
                mma8(sc[nf], av, b0, b1);
            }
        }

        // bias + mask + p = ex2(s); pack into PV A-fragments (registers)
        uint32_t pa[16];
        float s0 = 0.0f, s1 = 0.0f;
#pragma unroll
        for (int nf = 0; nf < 8; nf++) {
            int jc = nf * 8 + 2 * t4;
            float jk0 = (float)(k0g + jc);
            float2 ma = *(const float2*)&md[jc];
            float p0 = ex2(sc[nf][0] - BSC * fabsf(jk0 - tgtA) + ma.x);
            float p1 = ex2(sc[nf][1] - BSC * fabsf(jk0 + 1.0f - tgtA) + ma.y);
            float p2 = ex2(sc[nf][2] - BSC * fabsf(jk0 - tgtB) + ma.x);
            float p3 = ex2(sc[nf][3] - BSC * fabsf(jk0 + 1.0f - tgtB) + ma.y);
            s0 += p0 + p1;
            s1 += p2 + p3;
            pa[2 * nf]     = packh2(p0, p1);   // rows g
            pa[2 * nf + 1] = packh2(p2, p3);   // rows g+8
        }
        lp0 += s0;
        lp1 += s1;

        // O += P @ V  (A from registers; V^T B-frags from smem)
#pragma unroll
        for (int ks = 0; ks < 4; ks++) {
            const uint32_t cwB = (uint32_t)(((2 * ks + (tq & 1)) ^ i7) << 4);
            uint32_t bv[16];
#pragma unroll
            for (int np = 0; np < 4; np++)
                LDSM4(&bv[np * 4], VBc + laneB + np * 2048 + cwB);
#pragma unroll
            for (int nf = 0; nf < 8; nf++) {
                uint32_t b0 = bv[(nf >> 1) * 4 + (nf & 1) * 2];
                uint32_t b1 = bv[(nf >> 1) * 4 + (nf & 1) * 2 + 1];
                mma8(o[nf], &pa[4 * ks], b0, b1);
            }
        }
    }

    // ---- final row-sum reduction, normalize, write fp16 ----
    lp0 += __shfl_xor_sync(0xffffffffu, lp0, 1);
    lp0 += __shfl_xor_sync(0xffffffffu, lp0, 2);
    lp1 += __shfl_xor_sync(0xffffffffu, lp1, 1);
    lp1 += __shfl_xor_sync(0xffffffffu, lp1, 2);
    float inv0 = 1.0f / lp0;
    float inv1 = 1.0f / lp1;
    size_t r0 = ((size_t)(b * S_LEN + q0 + m0 + g)) * E_DIM + h * D_HEAD;
    size_t r1 = r0 + 8 * E_DIM;
#pragma unroll
    for (int nf = 0; nf < 8; nf++) {
        int col = nf * 8 + 2 * t4;
        *(__half2*)&out[r0 + col] =
            __floats2half2_rn(o[nf][0] * inv0, o[nf][1] * inv0);
        *(__half2*)&out[r1 + col] =
            __floats2half2_rn(o[nf][2] * inv1, o[nf][3] * inv1);
    }
}

// ---------------------------------------------------------------------------
extern "C" void kernel_launch(void* const* d_in, const int* in_sizes, int n_in,
                              void* d_out, int out_size)
{
    const float* x    = (const float*)d_in[0];
    const float* Wq   = (const float*)d_in[1];
    const float* Wk   = (const float*)d_in[2];
    const float* Wv   = (const float*)d_in[3];
    const float* Wo   = (const float*)d_in[4];
    const unsigned int* mask = (const unsigned int*)d_in[5];
    float* out = (float*)d_out;

    __half *xp, *wqp, *wkp, *wvp, *wop, *qp, *kp, *vp, *ap;
    cudaGetSymbolAddress((void**)&xp,  g_X);
    cudaGetSymbolAddress((void**)&wqp, g_Wq);
    cudaGetSymbolAddress((void**)&wkp, g_Wk);
    cudaGetSymbolAddress((void**)&wvp, g_Wv);
    cudaGetSymbolAddress((void**)&wop, g_Wo);
    cudaGetSymbolAddress((void**)&qp,  g_Q);
    cudaGetSymbolAddress((void**)&kp,  g_K);
    cudaGetSymbolAddress((void**)&vp,  g_V);
    cudaGetSymbolAddress((void**)&ap,  g_A);

    cudaFuncSetAttribute(gemm_tc, cudaFuncAttributeMaxDynamicSharedMemorySize, GEMM_SMEM);
    cudaFuncSetAttribute(attn_tc, cudaFuncAttributeMaxDynamicSharedMemorySize, ATT_SMEM);

    // 1. pre-convert inputs to fp16 (Wq scaled by 0.125*log2e)
    cvt_kernel<<<dim3(512, 1, 5), 256>>>((const float4*)x, (const float4*)Wq,
                                         (const float4*)Wk, (const float4*)Wv,
                                         (const float4*)Wo);

    // 2. fused QKV projections (V written transposed)
    gemm_tc<<<dim3(GN / 128, GM / 128, 3), 128, GEMM_SMEM>>>(
        xp, wqp, wkp, wvp, qp, kp, vp, 1);

    // 3. attention (q-tile 64, 4 warps x 16 rows, register P)
    attn_tc<<<dim3(S_LEN / 64, H_NUM, B_SZ), 128, ATT_SMEM>>>(mask, ap);

    // 4. output projection (fp32 out)
    gemm_tc<<<dim3(GN / 128, GM / 128, 1), 128, GEMM_SMEM>>>(
        ap, wop, wop, wop, out, out, out, 0);
}